// round 9
// baseline (speedup 1.0000x reference)
#include <cuda_runtime.h>
#include <math.h>

#define B_ 16
#define L_ 1024
#define CH 512
#define NCH 8192        // B_*CH
#define TPB 256
#define NSEG 48         // 3 scales * 16 batches
#define TOTL 1792       // 1024+512+256

#define IDX(i) ((i) + ((i) >> 5))   // smem pad: conflict-free FFT strides
#define ZSTR 1056                    // buffer stride: IDX(1023)+2

// ---------------- static scratch ----------------
__device__ float     g_qT[(size_t)NCH*L_];
__device__ float     g_kT[(size_t)NCH*L_];
__device__ float     g_vT[(size_t)NCH*L_];
__device__ float     g_outT[(size_t)NCH*L_];       // final summed rows, channel-major
__device__ unsigned  g_pkeys[(size_t)NCH*TOTL];    // per-channel peak keys
__device__ unsigned short g_ppos[(size_t)NCH*TOTL];// per-channel peak positions
__device__ int       g_chcnt[3*NCH];               // per-channel peak counts
__device__ float2    g_twid[896];
__device__ long long g_cmll[B_*TOTL];
__device__ long long g_sumll[NSEG];
__device__ long long g_sqll[NSEG];
__device__ int       g_kvals[NSEG];
__device__ int       g_krem[NSEG];
__device__ unsigned  g_prefix[NSEG];
__device__ float     g_thresh[NSEG];
__device__ int       g_pcount[NSEG];
__device__ unsigned  g_h4k[(size_t)NSEG*4096];     // zero-init; self-cleaned every pass
__device__ unsigned  g_done1[NSEG];
__device__ unsigned  g_done2[NSEG];

__constant__ int    cLs[3]    = {1024, 512, 256};
__constant__ int    cCmSeg[3] = {0, 16384, 24576};

#define SCCM 68719476736.0f   // 2^36 per-element cm fixed point
#define SCST 268435456.0      // 2^28 batch-stat fixed point (no int64 overflow)

__device__ __forceinline__ size_t corrOff(int s) {
    return s == 0 ? 0 : (s == 1 ? (size_t)NCH*1024 : (size_t)NCH*1536);
}
__device__ __forceinline__ unsigned f2k(float f) {
    unsigned u = __float_as_uint(f);
    return (u & 0x80000000u) ? ~u : (u | 0x80000000u);
}
__device__ __forceinline__ float k2f(unsigned k) {
    unsigned u = (k & 0x80000000u) ? (k & 0x7fffffffu) : ~k;
    return __uint_as_float(u);
}

// ---------------- init ----------------
__global__ void init_kernel() {
    int i = blockIdx.x * blockDim.x + threadIdx.x;
    int stride = gridDim.x * blockDim.x;
    for (int j = i; j < B_*TOTL; j += stride) g_cmll[j] = 0LL;
    if (i < NSEG) { g_sumll[i] = 0LL; g_sqll[i] = 0LL; g_pcount[i] = 0; }
    for (int j = i; j < 896; j += stride) {
        int N, jj;
        if (j < 512)      { N = 1024; jj = j; }
        else if (j < 768) { N = 512;  jj = j - 512; }
        else              { N = 256;  jj = j - 768; }
        double a = -6.283185307179586476925286766559 * (double)jj / (double)N;
        double sv, cv; sincos(a, &sv, &cv);
        g_twid[j] = make_float2((float)cv, (float)sv);
    }
}

// ---------------- transpose [B,L,CH] -> [B,CH,L] ----------------
__global__ void transpose3_kernel(const float* __restrict__ q,
                                  const float* __restrict__ k,
                                  const float* __restrict__ v) {
    __shared__ float tile[32][33];
    int b   = blockIdx.z;
    int ch0 = blockIdx.x * 32;
    int l0  = blockIdx.y * 32;
    const float* ins[3] = {q, k, v};
    float* outs[3] = {g_qT, g_kT, g_vT};
    int tx = threadIdx.x, ty = threadIdx.y;
    #pragma unroll
    for (int m = 0; m < 3; m++) {
        const float* in = ins[m];
        float* out = outs[m];
        for (int r = ty; r < 32; r += 8)
            tile[r][tx] = in[((size_t)b * L_ + (l0 + r)) * CH + ch0 + tx];
        __syncthreads();
        for (int r = ty; r < 32; r += 8)
            out[((size_t)b * CH + (ch0 + r)) * L_ + l0 + tx] = tile[tx][r];
        __syncthreads();
    }
}

// ---------------- radix-4 (merged radix-2 pairs) in-place DIT FFT, padded smem ----------------
__device__ __forceinline__ void fft_pairs(float* sr, float* si, int N, int logN,
                                          const float2* __restrict__ tw, bool inv, int tid) {
    int st = 1;
    if (logN & 1) {
        for (int j = tid; j < (N >> 1); j += TPB) {
            int i0 = IDX(j << 1), i1 = IDX((j << 1) + 1);
            float ur = sr[i0], ui = si[i0], vr = sr[i1], vi = si[i1];
            sr[i0] = ur + vr; si[i0] = ui + vi;
            sr[i1] = ur - vr; si[i1] = ui - vi;
        }
        __syncthreads();
        st = 2;
    }
    int groups = N >> 2;
    for (; st < logN; st += 2) {
        int half = 1 << (st - 1);
        for (int g = tid; g < groups; g += TPB) {
            int pos = g & (half - 1);
            int blk = g >> (st - 1);
            int a0 = (blk << (st + 1)) + pos;
            int i0 = IDX(a0), i1 = IDX(a0 + half), i2 = IDX(a0 + 2*half), i3 = IDX(a0 + 3*half);
            float2 w  = tw[pos << (logN - st - 1)];
            float2 w2 = tw[pos << (logN - st)];
            float wbr = w.x,  wbi = inv ? -w.y  : w.y;
            float war = w2.x, wai = inv ? -w2.y : w2.y;
            float a0r = sr[i0], a0i = si[i0], a1r = sr[i1], a1i = si[i1];
            float a2r = sr[i2], a2i = si[i2], a3r = sr[i3], a3i = si[i3];
            float t1r = war*a1r - wai*a1i, t1i = war*a1i + wai*a1r;
            float b0r = a0r + t1r, b0i = a0i + t1i;
            float b1r = a0r - t1r, b1i = a0i - t1i;
            float t3r = war*a3r - wai*a3i, t3i = war*a3i + wai*a3r;
            float b2r = a2r + t3r, b2i = a2i + t3i;
            float b3r = a2r - t3r, b3i = a2i - t3i;
            float u2r = wbr*b2r - wbi*b2i, u2i = wbr*b2i + wbi*b2r;
            float u3r = wbr*b3r - wbi*b3i, u3i = wbr*b3i + wbi*b3r;
            float vr3, vi3;
            if (!inv) { vr3 =  u3i; vi3 = -u3r; }
            else      { vr3 = -u3i; vi3 =  u3r; }
            sr[i0] = b0r + u2r; si[i0] = b0i + u2i;
            sr[i2] = b0r - u2r; si[i2] = b0i - u2i;
            sr[i1] = b1r + vr3; si[i1] = b1i + vi3;
            sr[i3] = b1r - vr3; si[i3] = b1i - vi3;
        }
        __syncthreads();
    }
}

__device__ __forceinline__ void split_mult(const float* zr, const float* zi,
                                           float* wr, float* wi, int Ls, int shv, int tid) {
    for (int f = tid; f <= Ls / 2; f += TPB) {
        int g = (Ls - f) & (Ls - 1);
        float a = zr[IDX(f)], bq = zi[IDX(f)];
        float c = zr[IDX(g)], d  = zi[IDX(g)];
        float qr = 0.5f * (a + c),  qi = 0.5f * (bq - d);
        float kr = 0.5f * (bq + d), ki = 0.5f * (a - c);
        float Sr = qr * kr - qi * ki;
        float Si = qr * ki + qi * kr;
        int pf = IDX((int)(__brev((unsigned)f) >> shv));
        int pg = IDX((int)(__brev((unsigned)g) >> shv));
        wr[pf] = Sr; wi[pf] = Si;
        wr[pg] = Sr; wi[pg] = -Si;
    }
}

__device__ __forceinline__ void derive_half(float* zr, float* zi, int Lout,
                                            const float2* __restrict__ twN, int tid) {
    for (int f = tid; f < Lout; f += TPB) {
        float2 t = twN[f];
        float er = t.x, ei = -t.y;
        float ar = zr[IDX(f)],        ai = zi[IDX(f)];
        float br = zr[IDX(f + Lout)], bi = zi[IDX(f + Lout)];
        float p1r = ar * (1.0f + er) - ai * ei;
        float p1i = ai * (1.0f + er) + ar * ei;
        float p2r = br * (1.0f - er) + bi * ei;
        float p2i = bi * (1.0f - er) - br * ei;
        zr[IDX(f)] = 0.25f * (p1r + p2r);
        zi[IDX(f)] = 0.25f * (p1i + p2i);
    }
}

// Per-scale epilogue: stats/cm atomics + peak (key,pos) compaction + pass-0 histogram.
// NOTE: corr is never written to global anymore.
__device__ void epilogue(int sIdx, int ch, int b, int seg, int Ls, const float* wr,
                         int tid, double* wsum, double* wsq, int* s_cnt) {
    const float invN = 1.0f / (float)Ls;
    int lane = tid & 31;
    double sm = 0.0, sq = 0.0;
    int nv = Ls >> 2;
    if (tid == 0) *s_cnt = 0;
    if (tid < nv) {
        int t0 = tid * 4;
        int i0 = IDX(t0);
        float v0 = wr[i0] * invN, v1 = wr[i0+1] * invN, v2 = wr[i0+2] * invN, v3 = wr[i0+3] * invN;
        sm = (double)v0 + (double)v1 + (double)v2 + (double)v3;
        sq = (double)v0*v0 + (double)v1*v1 + (double)v2*v2 + (double)v3*v3;
        long long* cmp = g_cmll + cCmSeg[sIdx] + b * Ls + t0;
        atomicAdd((unsigned long long*)(cmp  ), (unsigned long long)__float2ll_rn(v0 * SCCM));
        atomicAdd((unsigned long long*)(cmp+1), (unsigned long long)__float2ll_rn(v1 * SCCM));
        atomicAdd((unsigned long long*)(cmp+2), (unsigned long long)__float2ll_rn(v2 * SCCM));
        atomicAdd((unsigned long long*)(cmp+3), (unsigned long long)__float2ll_rn(v3 * SCCM));
    }
    #pragma unroll
    for (int off = 16; off > 0; off >>= 1) {
        sm += __shfl_down_sync(0xffffffffu, sm, off);
        sq += __shfl_down_sync(0xffffffffu, sq, off);
    }
    if (lane == 0) { wsum[tid >> 5] = sm; wsq[tid >> 5] = sq; }
    __syncthreads();
    if (tid == 0) {
        double ts = 0.0, tq = 0.0;
        #pragma unroll
        for (int w = 0; w < 8; w++) { ts += wsum[w]; tq += wsq[w]; }
        atomicAdd((unsigned long long*)&g_sumll[seg], (unsigned long long)__double2ll_rn(ts * SCST));
        atomicAdd((unsigned long long*)&g_sqll[seg],  (unsigned long long)__double2ll_rn(tq * SCST));
    }

    // peak detection: write per-channel (key,pos) + pass-0 histogram
    unsigned* keys = g_pkeys + corrOff(sIdx) + (size_t)ch * Ls;
    unsigned short* ppos = g_ppos + corrOff(sIdx) + (size_t)ch * Ls;
    unsigned* gh0 = g_h4k + (size_t)seg * 4096;
    int iters = Ls / TPB;
    for (int it = 0; it < iters; it++) {
        int t = it * TPB + tid + 1;
        bool pk = false; float v = 0.0f;
        if (t < Ls - 1) {
            v = wr[IDX(t)];
            pk = (v > wr[IDX(t-1)] && v > wr[IDX(t+1)]);
        }
        unsigned key = pk ? f2k(v * invN) : 0u;
        if (pk) {
            int p = atomicAdd(s_cnt, 1);
            keys[p] = key;
            ppos[p] = (unsigned short)t;
        }
        unsigned tag = pk ? (key >> 20) : 0xffffffffu;
        unsigned mm = __match_any_sync(0xffffffffu, tag);
        if (pk && lane == (__ffs(mm) - 1))
            atomicAdd(&gh0[key >> 20], (unsigned)__popc(mm));
    }
    __syncthreads();
    if (tid == 0) {
        int c = *s_cnt;
        g_chcnt[sIdx * NCH + ch] = c;
        atomicAdd(&g_pcount[seg], c);
    }
    __syncthreads();
}

// ---------------- fused corr: 1 fwd FFT + spectral pooling + 3 inverse FFTs ----------------
__global__ void corr_fused_kernel() {
    extern __shared__ float smem[];
    __shared__ double wsum[8], wsq[8];
    __shared__ int s_cnt;
    int ch = blockIdx.x;
    int b  = ch >> 9;
    float* zr = smem;
    float* zi = smem + ZSTR;
    float* wr = smem + 2 * ZSTR;
    float* wi = smem + 3 * ZSTR;
    int tid = threadIdx.x;

    {
        float4 qa = ((const float4*)(g_qT + (size_t)ch * L_))[tid];
        float4 ka = ((const float4*)(g_kT + (size_t)ch * L_))[tid];
        int t0 = tid * 4;
        int r0 = IDX((int)(__brev((unsigned)(t0  )) >> 22));
        int r1 = IDX((int)(__brev((unsigned)(t0+1)) >> 22));
        int r2 = IDX((int)(__brev((unsigned)(t0+2)) >> 22));
        int r3 = IDX((int)(__brev((unsigned)(t0+3)) >> 22));
        zr[r0] = qa.x; zi[r0] = ka.x;
        zr[r1] = qa.y; zi[r1] = ka.y;
        zr[r2] = qa.z; zi[r2] = ka.z;
        zr[r3] = qa.w; zi[r3] = ka.w;
    }
    __syncthreads();

    fft_pairs(zr, zi, 1024, 10, g_twid, false, tid);

    split_mult(zr, zi, wr, wi, 1024, 22, tid);
    __syncthreads();
    fft_pairs(wr, wi, 1024, 10, g_twid, true, tid);
    epilogue(0, ch, b, b, 1024, wr, tid, wsum, wsq, &s_cnt);

    derive_half(zr, zi, 512, g_twid, tid);
    __syncthreads();
    split_mult(zr, zi, wr, wi, 512, 23, tid);
    __syncthreads();
    fft_pairs(wr, wi, 512, 9, g_twid + 512, true, tid);
    epilogue(1, ch, b, 16 + b, 512, wr, tid, wsum, wsq, &s_cnt);

    derive_half(zr, zi, 256, g_twid + 512, tid);
    __syncthreads();
    split_mult(zr, zi, wr, wi, 256, 24, tid);
    __syncthreads();
    fft_pairs(wr, wi, 256, 8, g_twid + 768, true, tid);
    epilogue(2, ch, b, 32 + b, 256, wr, tid, wsum, wsq, &s_cnt);
}

// ---------------- scan0: pk feature + MLP + scan pass-0 hist ----------------
__global__ void scan0_kernel(const float* __restrict__ w1, const float* __restrict__ b1,
                             const float* __restrict__ w2, const float* __restrict__ b2,
                             const float* __restrict__ w3, const float* __restrict__ b3) {
    __shared__ unsigned sscan[TPB];
    __shared__ int s_pkred[8];
    __shared__ int s_k;
    int seg = blockIdx.x;
    int sIdx = seg >> 4, b = seg & 15;
    int Ls = cLs[sIdx];
    int tid = threadIdx.x;
    int lane = tid & 31;
    unsigned* hist = g_h4k + (size_t)seg * 4096;

    const long long* cm = g_cmll + cCmSeg[sIdx] + b * Ls;
    int cnt = 0;
    for (int t = tid + 1; t < Ls - 1; t += TPB) {
        long long v = cm[t];
        if (v > cm[t - 1] && v > cm[t + 1]) cnt++;
    }
    #pragma unroll
    for (int off = 16; off > 0; off >>= 1) cnt += __shfl_down_sync(0xffffffffu, cnt, off);
    if (lane == 0) s_pkred[tid >> 5] = cnt;
    __syncthreads();
    if (tid == 0) {
        int pkc = 0;
        #pragma unroll
        for (int w = 0; w < 8; w++) pkc += s_pkred[w];
        const double invSC = 1.0 / SCST;
        float f2 = (float)pkc;
        long long tot = 0;
        for (int i = 0; i < B_; i++) tot += g_sqll[sIdx * 16 + i];
        float f0 = (float)((double)tot * invSC / ((double)B_ * (double)Ls));
        double n = (double)CH * (double)Ls;
        double s1 = (double)g_sumll[seg] * invSC;
        double s2 = (double)g_sqll[seg] * invSC;
        double mean = s1 / n;
        float f1 = (float)((s2 - mean * s1) / (n - 1.0));
        float h1[32];
        for (int j = 0; j < 32; j++) {
            float a = w1[j*3] * f0 + w1[j*3+1] * f1 + w1[j*3+2] * f2 + b1[j];
            h1[j] = a > 0.0f ? a : 0.0f;
        }
        float h2[16];
        for (int j = 0; j < 16; j++) {
            float a = b2[j];
            for (int i2 = 0; i2 < 32; i2++) a += w2[j*32+i2] * h1[i2];
            h2[j] = a > 0.0f ? a : 0.0f;
        }
        float a = b3[0];
        for (int i2 = 0; i2 < 16; i2++) a += w3[i2] * h2[i2];
        float ratio = 1.0f / (1.0f + expf(-a));
        int kv = (int)(ratio * (float)Ls);
        if (kv < 1) kv = 1;
        if (kv > Ls) kv = Ls;
        g_kvals[seg] = kv;
        s_k = kv;
    }
    __syncthreads();
    unsigned k = (unsigned)s_k;

    int cstart = tid * 16;
    unsigned myChunk = 0;
    uint4 hb[4];
    {
        const uint4* h4 = (const uint4*)(hist + cstart);
        #pragma unroll
        for (int j = 0; j < 4; j++) {
            hb[j] = h4[j];
            myChunk += hb[j].x + hb[j].y + hb[j].z + hb[j].w;
        }
    }
    sscan[tid] = myChunk;
    __syncthreads();
    for (int off = 1; off < TPB; off <<= 1) {
        unsigned v = (tid + off < TPB) ? sscan[tid + off] : 0u;
        __syncthreads();
        sscan[tid] += v;
        __syncthreads();
    }
    unsigned incl = sscan[tid];
    unsigned cumBefore = incl - myChunk;
    if (myChunk > 0 && cumBefore < k && incl >= k) {
        unsigned cum = cumBefore;
        unsigned bins[16] = {hb[0].x,hb[0].y,hb[0].z,hb[0].w, hb[1].x,hb[1].y,hb[1].z,hb[1].w,
                             hb[2].x,hb[2].y,hb[2].z,hb[2].w, hb[3].x,hb[3].y,hb[3].z,hb[3].w};
        for (int j = 15; j >= 0; --j) {
            unsigned h = bins[j];
            if (cum + h >= k) {
                g_prefix[seg] = (unsigned)(cstart + j) << 20;
                g_krem[seg] = (int)(k - cum);
                break;
            }
            cum += h;
        }
    }
    {
        uint4* h4 = (uint4*)(hist + cstart);
        #pragma unroll
        for (int j = 0; j < 4; j++) h4[j] = make_uint4(0u,0u,0u,0u);
    }
}

// ---------------- fused hist+scan passes 1 (12 bits) and 2 (8 bits), per-channel lists ----------------
__global__ void histscan_kernel(int pass) {
    __shared__ unsigned hl[4096];
    __shared__ unsigned sscan[TPB];
    __shared__ int s_last, s_k;
    int seg = blockIdx.y;
    int sIdx = seg >> 4, b = seg & 15;
    int Ls = cLs[sIdx];
    int tid = threadIdx.x;
    int lane = tid & 31;
    unsigned* gh = g_h4k + (size_t)seg * 4096;
    unsigned* ctr = (pass == 1 ? g_done1 : g_done2) + seg;

    for (int i = tid; i < 4096; i += TPB) hl[i] = 0;
    __syncthreads();

    unsigned pref = g_prefix[seg];
    // this block handles 16 channels of the batch
    int c0 = blockIdx.x * 16;
    for (int cc = 0; cc < 16; cc++) {
        int ch = b * CH + c0 + cc;
        int cnt = g_chcnt[sIdx * NCH + ch];
        const unsigned* keys = g_pkeys + corrOff(sIdx) + (size_t)ch * Ls;
        int iters = (cnt + TPB - 1) / TPB;
        for (int it = 0; it < iters; it++) {
            int i = it * TPB + tid;
            bool valid = (i < cnt);
            unsigned key = valid ? keys[i] : 0u;
            bool ok; unsigned bin;
            if (pass == 1) { ok = valid && ((key >> 20) == (pref >> 20)); bin = (key >> 8) & 0xfffu; }
            else           { ok = valid && ((key >> 8) == (pref >> 8));   bin = key & 0xffu; }
            unsigned tag = ok ? bin : 0xffffffffu;
            unsigned mm = __match_any_sync(0xffffffffu, tag);
            if (ok && lane == (__ffs(mm) - 1))
                atomicAdd(&hl[bin], (unsigned)__popc(mm));
        }
    }
    __syncthreads();
    for (int j = tid; j < 4096; j += TPB)
        if (hl[j]) atomicAdd(&gh[j], hl[j]);
    __threadfence();
    if (tid == 0) {
        unsigned t = atomicAdd(ctr, 1u);
        s_last = (t == gridDim.x - 1) ? 1 : 0;
    }
    __syncthreads();
    if (!s_last) return;
    __threadfence();
    if (tid == 0) s_k = g_krem[seg];
    __syncthreads();
    unsigned k = (unsigned)s_k;

    int nb = (pass == 2) ? 256 : 4096;
    int bpt = nb / TPB;
    int cstart = tid * bpt;
    unsigned myChunk = 0;
    for (int j = 0; j < bpt; j++) myChunk += gh[cstart + j];
    sscan[tid] = myChunk;
    __syncthreads();
    for (int off = 1; off < TPB; off <<= 1) {
        unsigned v = (tid + off < TPB) ? sscan[tid + off] : 0u;
        __syncthreads();
        sscan[tid] += v;
        __syncthreads();
    }
    unsigned incl = sscan[tid];
    unsigned cumBefore = incl - myChunk;
    if (myChunk > 0 && cumBefore < k && incl >= k) {
        unsigned cum = cumBefore;
        for (int bin = cstart + bpt - 1; bin >= cstart; --bin) {
            unsigned h = gh[bin];
            if (cum + h >= k) {
                if (pass == 1) {
                    g_prefix[seg] = (pref & 0xfff00000u) | ((unsigned)bin << 8);
                    g_krem[seg] = (int)(k - cum);
                } else {
                    g_thresh[seg] = k2f((pref & 0xffffff00u) | (unsigned)bin);
                }
                break;
            }
            cum += h;
        }
    }
    __syncthreads();
    for (int j = tid; j < 4096; j += TPB) gh[j] = 0u;
    if (tid == 0) *ctr = 0u;
}

// ---------------- final: peak-list softmax * pooled v + interp + sum, one block per channel ----------------
__global__ void final_combined_kernel(const float* __restrict__ swarr) {
    __shared__ float wrow[1024];
    __shared__ float acc[1024];
    __shared__ float vsm[1024];
    __shared__ float redf[8];
    __shared__ int   redi[8];
    __shared__ float s_bc0, s_bc1;
    __shared__ int   s_bci;
    int ch = blockIdx.x;
    int b  = ch >> 9;
    int tid = threadIdx.x;
    int lane = tid & 31, wid = tid >> 5;

    ((float4*)vsm)[tid] = ((const float4*)(g_vT + (size_t)ch * L_))[tid];
    __syncthreads();

    for (int sIdx = 0; sIdx < 3; sIdx++) {
        int Ls = cLs[sIdx];
        int seg = sIdx * 16 + b;
        int cnt = g_chcnt[sIdx * NCH + ch];
        float thr = g_thresh[seg];
        bool useAll = (g_pcount[seg] <= g_kvals[seg]);
        const unsigned* keys = g_pkeys + corrOff(sIdx) + (size_t)ch * Ls;
        const float sw = swarr[sIdx];

        // pass 1: max over selected peaks (m >= 0 since zeros always present)
        float lmax = 0.0f;
        for (int i = tid; i < cnt; i += TPB) {
            float v = k2f(keys[i]);
            if (useAll || v >= thr) lmax = fmaxf(lmax, v);
        }
        #pragma unroll
        for (int off = 16; off > 0; off >>= 1)
            lmax = fmaxf(lmax, __shfl_down_sync(0xffffffffu, lmax, off));
        if (lane == 0) redf[wid] = lmax;
        __syncthreads();
        if (tid == 0) {
            float m = 0.0f;
            #pragma unroll
            for (int w = 0; w < 8; w++) m = fmaxf(m, redf[w]);
            s_bc0 = m;
        }
        __syncthreads();
        float m = s_bc0;
        __syncthreads();

        // pass 2: denom = sum_sel exp(v-m) + (Ls - nsel) * exp(-m)
        float lsum = 0.0f; int lsel = 0;
        for (int i = tid; i < cnt; i += TPB) {
            float v = k2f(keys[i]);
            if (useAll || v >= thr) { lsum += __expf(v - m); lsel++; }
        }
        #pragma unroll
        for (int off = 16; off > 0; off >>= 1) {
            lsum += __shfl_down_sync(0xffffffffu, lsum, off);
            lsel += __shfl_down_sync(0xffffffffu, lsel, off);
        }
        if (lane == 0) { redf[wid] = lsum; redi[wid] = lsel; }
        __syncthreads();
        if (tid == 0) {
            float ts = 0.0f; int tc = 0;
            #pragma unroll
            for (int w = 0; w < 8; w++) { ts += redf[w]; tc += redi[w]; }
            float base = __expf(-m);
            float denom = ts + (float)(Ls - tc) * base;
            float inv = 1.0f / denom;
            s_bc1 = base * inv;     // baseline weight
            s_bc0 = inv;
            s_bci = 0;
        }
        __syncthreads();
        float inv = s_bc0;
        float wbase = s_bc1;

        // fill + scatter weights
        for (int t = tid; t < Ls; t += TPB) wrow[t] = wbase;
        __syncthreads();
        const unsigned short* ppos = g_ppos + corrOff(sIdx) + (size_t)ch * Ls;
        for (int i = tid; i < cnt; i += TPB) {
            float v = k2f(keys[i]);
            if (useAll || v >= thr) wrow[ppos[i]] = __expf(v - m) * inv;
        }
        __syncthreads();

        // multiply by scale weight * pooled v, then interpolate+accumulate
        if (sIdx == 0) {
            int t0 = tid * 4;
            #pragma unroll
            for (int j = 0; j < 4; j++)
                acc[t0 + j] = sw * wrow[t0 + j] * vsm[t0 + j];
        } else if (sIdx == 1) {
            int t0 = tid * 2;
            #pragma unroll
            for (int j = 0; j < 2; j++)
                wrow[t0 + j] = sw * wrow[t0 + j] * (0.5f * (vsm[2*(t0+j)] + vsm[2*(t0+j)+1]));
            __syncthreads();
            for (int l = tid; l < 1024; l += TPB) {
                float s1 = 0.5f * (float)l - 0.25f; if (s1 < 0.0f) s1 = 0.0f;
                int x0 = (int)s1; int x1 = x0 + 1; if (x1 > 511) x1 = 511;
                float lam = s1 - (float)x0;
                acc[l] += wrow[x0] * (1.0f - lam) + wrow[x1] * lam;
            }
        } else {
            if (tid < 256) {
                int j = tid;
                wrow[j] = sw * wrow[j] * (0.25f * (vsm[4*j] + vsm[4*j+1] + vsm[4*j+2] + vsm[4*j+3]));
            }
            __syncthreads();
            for (int l = tid; l < 1024; l += TPB) {
                float s2 = 0.25f * (float)l - 0.375f; if (s2 < 0.0f) s2 = 0.0f;
                int x0 = (int)s2; int x1 = x0 + 1; if (x1 > 255) x1 = 255;
                float lam = s2 - (float)x0;
                acc[l] += wrow[x0] * (1.0f - lam) + wrow[x1] * lam;
            }
        }
        __syncthreads();
    }

    ((float4*)(g_outT + (size_t)ch * L_))[tid] = ((const float4*)acc)[tid];
}

// ---------------- untranspose [B,CH,L] -> [B,L,CH] ----------------
__global__ void untranspose_kernel(float* __restrict__ out) {
    __shared__ float tile[32][33];
    int b   = blockIdx.z;
    int ch0 = blockIdx.x * 32;
    int l0  = blockIdx.y * 32;
    int tx = threadIdx.x, ty = threadIdx.y;
    for (int r = ty; r < 32; r += 8)
        tile[r][tx] = g_outT[((size_t)b * CH + (ch0 + r)) * L_ + l0 + tx];
    __syncthreads();
    for (int r = ty; r < 32; r += 8)
        out[((size_t)b * L_ + (l0 + r)) * CH + ch0 + tx] = tile[tx][r];
}

// ---------------- launch ----------------
extern "C" void kernel_launch(void* const* d_in, const int* in_sizes, int n_in,
                              void* d_out, int out_size) {
    (void)in_sizes; (void)n_in; (void)out_size;
    const float* q  = (const float*)d_in[0];
    const float* kk = (const float*)d_in[1];
    const float* v  = (const float*)d_in[2];
    const float* sw = (const float*)d_in[3];
    const float* w1 = (const float*)d_in[4];
    const float* b1 = (const float*)d_in[5];
    const float* w2 = (const float*)d_in[6];
    const float* b2 = (const float*)d_in[7];
    const float* w3 = (const float*)d_in[8];
    const float* b3 = (const float*)d_in[9];
    float* out = (float*)d_out;

    init_kernel<<<64, TPB>>>();

    dim3 tgrid(CH / 32, L_ / 32, B_);
    dim3 tblk(32, 8);
    transpose3_kernel<<<tgrid, tblk>>>(q, kk, v);

    int fftSmem = 4 * ZSTR * sizeof(float);
    corr_fused_kernel<<<NCH, TPB, fftSmem>>>();

    scan0_kernel<<<NSEG, TPB>>>(w1, b1, w2, b2, w3, b3);
    dim3 hg(32, NSEG);
    histscan_kernel<<<hg, TPB>>>(1);
    histscan_kernel<<<hg, TPB>>>(2);

    final_combined_kernel<<<NCH, TPB>>>(sw);

    untranspose_kernel<<<tgrid, tblk>>>(out);
}

// round 10
// speedup vs baseline: 1.0457x; 1.0457x over previous
#include <cuda_runtime.h>
#include <math.h>

#define B_ 16
#define L_ 1024
#define CH 512
#define NCH 8192        // B_*CH
#define TPB 256
#define NSEG 48         // 3 scales * 16 batches
#define TOTL 1792       // 1024+512+256

#define IDX(i) ((i) + ((i) >> 5))   // smem pad: conflict-free FFT strides
#define ZSTR 1056                    // buffer stride: IDX(1023)+2

// ---------------- static scratch ----------------
__device__ float     g_qT[(size_t)NCH*L_];
__device__ float     g_kT[(size_t)NCH*L_];
__device__ float     g_vT[(size_t)NCH*L_];
__device__ float     g_corr[(size_t)NCH*TOTL];
__device__ float     g_wv[(size_t)NCH*TOTL];      // weighted softmax*v rows (pre-interp)
__device__ unsigned  g_pkeys[(size_t)NCH*TOTL];
__device__ float2    g_twid[896];
__device__ long long g_cmll[B_*TOTL];
__device__ long long g_sumll[NSEG];
__device__ long long g_sqll[NSEG];
__device__ int       g_kvals[NSEG];
__device__ int       g_krem[NSEG];
__device__ unsigned  g_prefix[NSEG];
__device__ float     g_thresh[NSEG];
__device__ int       g_pcount[NSEG];
__device__ unsigned  g_h4k[(size_t)NSEG*4096];    // zero-init; self-cleaned every pass
__device__ unsigned  g_done1[NSEG];               // ticket counters; self-reset
__device__ unsigned  g_done2[NSEG];

__constant__ int    cLs[3]    = {1024, 512, 256};
__constant__ int    cCmSeg[3] = {0, 16384, 24576};

#define SCCM 68719476736.0f   // 2^36 per-element cm fixed point
#define SCST 268435456.0      // 2^28 batch-stat fixed point (no int64 overflow)

__device__ __forceinline__ size_t corrOff(int s) {
    return s == 0 ? 0 : (s == 1 ? (size_t)NCH*1024 : (size_t)NCH*1536);
}
__device__ __forceinline__ unsigned f2k(float f) {
    unsigned u = __float_as_uint(f);
    return (u & 0x80000000u) ? ~u : (u | 0x80000000u);
}
__device__ __forceinline__ float k2f(unsigned k) {
    unsigned u = (k & 0x80000000u) ? (k & 0x7fffffffu) : ~k;
    return __uint_as_float(u);
}

// ---------------- init ----------------
__global__ void init_kernel() {
    int i = blockIdx.x * blockDim.x + threadIdx.x;
    int stride = gridDim.x * blockDim.x;
    for (int j = i; j < B_*TOTL; j += stride) g_cmll[j] = 0LL;
    if (i < NSEG) { g_sumll[i] = 0LL; g_sqll[i] = 0LL; g_pcount[i] = 0; }
    for (int j = i; j < 896; j += stride) {
        int N, jj;
        if (j < 512)      { N = 1024; jj = j; }
        else if (j < 768) { N = 512;  jj = j - 512; }
        else              { N = 256;  jj = j - 768; }
        double a = -6.283185307179586476925286766559 * (double)jj / (double)N;
        double sv, cv; sincos(a, &sv, &cv);
        g_twid[j] = make_float2((float)cv, (float)sv);
    }
}

// ---------------- transpose [B,L,CH] -> [B,CH,L] ----------------
__global__ void transpose3_kernel(const float* __restrict__ q,
                                  const float* __restrict__ k,
                                  const float* __restrict__ v) {
    __shared__ float tile[32][33];
    int b   = blockIdx.z;
    int ch0 = blockIdx.x * 32;
    int l0  = blockIdx.y * 32;
    const float* ins[3] = {q, k, v};
    float* outs[3] = {g_qT, g_kT, g_vT};
    int tx = threadIdx.x, ty = threadIdx.y;
    #pragma unroll
    for (int m = 0; m < 3; m++) {
        const float* in = ins[m];
        float* out = outs[m];
        for (int r = ty; r < 32; r += 8)
            tile[r][tx] = in[((size_t)b * L_ + (l0 + r)) * CH + ch0 + tx];
        __syncthreads();
        for (int r = ty; r < 32; r += 8)
            out[((size_t)b * CH + (ch0 + r)) * L_ + l0 + tx] = tile[tx][r];
        __syncthreads();
    }
}

// ---------------- radix-4 FFT on smem, twiddles from a shared 512-entry 1024-pt table ----------------
// tw_N[j] == tw1024[j * (1024/N)]  =>  stage indices depend only on st, not N.
__device__ __forceinline__ void fft_pairs(float* sr, float* si, int N, int logN,
                                          const float2* tws, bool inv, int tid) {
    int st = 1;
    if (logN & 1) {
        for (int j = tid; j < (N >> 1); j += TPB) {
            int i0 = IDX(j << 1), i1 = IDX((j << 1) + 1);
            float ur = sr[i0], ui = si[i0], vr = sr[i1], vi = si[i1];
            sr[i0] = ur + vr; si[i0] = ui + vi;
            sr[i1] = ur - vr; si[i1] = ui - vi;
        }
        __syncthreads();
        st = 2;
    }
    int groups = N >> 2;
    for (; st < logN; st += 2) {
        int half = 1 << (st - 1);
        for (int g = tid; g < groups; g += TPB) {
            int pos = g & (half - 1);
            int blk = g >> (st - 1);
            int a0 = (blk << (st + 1)) + pos;
            int i0 = IDX(a0), i1 = IDX(a0 + half), i2 = IDX(a0 + 2*half), i3 = IDX(a0 + 3*half);
            float2 w  = tws[pos << (9 - st)];
            float2 w2 = tws[pos << (10 - st)];
            float wbr = w.x,  wbi = inv ? -w.y  : w.y;
            float war = w2.x, wai = inv ? -w2.y : w2.y;
            float a0r = sr[i0], a0i = si[i0], a1r = sr[i1], a1i = si[i1];
            float a2r = sr[i2], a2i = si[i2], a3r = sr[i3], a3i = si[i3];
            float t1r = war*a1r - wai*a1i, t1i = war*a1i + wai*a1r;
            float b0r = a0r + t1r, b0i = a0i + t1i;
            float b1r = a0r - t1r, b1i = a0i - t1i;
            float t3r = war*a3r - wai*a3i, t3i = war*a3i + wai*a3r;
            float b2r = a2r + t3r, b2i = a2i + t3i;
            float b3r = a2r - t3r, b3i = a2i - t3i;
            float u2r = wbr*b2r - wbi*b2i, u2i = wbr*b2i + wbi*b2r;
            float u3r = wbr*b3r - wbi*b3i, u3i = wbr*b3i + wbi*b3r;
            float vr3, vi3;
            if (!inv) { vr3 =  u3i; vi3 = -u3r; }
            else      { vr3 = -u3i; vi3 =  u3r; }
            sr[i0] = b0r + u2r; si[i0] = b0i + u2i;
            sr[i2] = b0r - u2r; si[i2] = b0i - u2i;
            sr[i1] = b1r + vr3; si[i1] = b1i + vi3;
            sr[i3] = b1r - vr3; si[i3] = b1i - vi3;
        }
        __syncthreads();
    }
}

__device__ __forceinline__ void split_mult(const float* zr, const float* zi,
                                           float* wr, float* wi, int Ls, int shv, int tid) {
    for (int f = tid; f <= Ls / 2; f += TPB) {
        int g = (Ls - f) & (Ls - 1);
        float a = zr[IDX(f)], bq = zi[IDX(f)];
        float c = zr[IDX(g)], d  = zi[IDX(g)];
        float qr = 0.5f * (a + c),  qi = 0.5f * (bq - d);
        float kr = 0.5f * (bq + d), ki = 0.5f * (a - c);
        float Sr = qr * kr - qi * ki;
        float Si = qr * ki + qi * kr;
        int pf = IDX((int)(__brev((unsigned)f) >> shv));
        int pg = IDX((int)(__brev((unsigned)g) >> shv));
        wr[pf] = Sr; wi[pf] = Si;
        wr[pg] = Sr; wi[pg] = -Si;
    }
}

// Z_out[f] = 0.25*( Z[f]*(1+e) + Z[f+Lout]*(1-e) ), e = conj(tw_{2Lout}[f]) = conj(tws[f<<shiftTw]).
__device__ __forceinline__ void derive_half(float* zr, float* zi, int Lout, int shiftTw,
                                            const float2* tws, int tid) {
    for (int f = tid; f < Lout; f += TPB) {
        float2 t = tws[f << shiftTw];
        float er = t.x, ei = -t.y;
        float ar = zr[IDX(f)],        ai = zi[IDX(f)];
        float br = zr[IDX(f + Lout)], bi = zi[IDX(f + Lout)];
        float p1r = ar * (1.0f + er) - ai * ei;
        float p1i = ai * (1.0f + er) + ar * ei;
        float p2r = br * (1.0f - er) + bi * ei;
        float p2i = bi * (1.0f - er) - br * ei;
        zr[IDX(f)] = 0.25f * (p1r + p2r);
        zi[IDX(f)] = 0.25f * (p1i + p2i);
    }
}

// Per-scale epilogue: write corr row, stats/cm atomics, peak compaction + pass-0 histogram.
__device__ void epilogue(int sIdx, int ch, int b, int seg, int Ls, const float* wr,
                         int tid, double* wsum, double* wsq, int* s_cnt, int* s_base) {
    const float invN = 1.0f / (float)Ls;
    int lane = tid & 31;
    float* outRow = g_corr + corrOff(sIdx) + (size_t)ch * Ls;
    double sm = 0.0, sq = 0.0;
    int nv = Ls >> 2;
    if (tid == 0) *s_cnt = 0;
    if (tid < nv) {
        int t0 = tid * 4;
        int i0 = IDX(t0);
        float v0 = wr[i0] * invN, v1 = wr[i0+1] * invN, v2 = wr[i0+2] * invN, v3 = wr[i0+3] * invN;
        ((float4*)outRow)[tid] = make_float4(v0, v1, v2, v3);
        sm = (double)v0 + (double)v1 + (double)v2 + (double)v3;
        sq = (double)v0*v0 + (double)v1*v1 + (double)v2*v2 + (double)v3*v3;
        long long* cmp = g_cmll + cCmSeg[sIdx] + b * Ls + t0;
        atomicAdd((unsigned long long*)(cmp  ), (unsigned long long)__float2ll_rn(v0 * SCCM));
        atomicAdd((unsigned long long*)(cmp+1), (unsigned long long)__float2ll_rn(v1 * SCCM));
        atomicAdd((unsigned long long*)(cmp+2), (unsigned long long)__float2ll_rn(v2 * SCCM));
        atomicAdd((unsigned long long*)(cmp+3), (unsigned long long)__float2ll_rn(v3 * SCCM));
    }
    #pragma unroll
    for (int off = 16; off > 0; off >>= 1) {
        sm += __shfl_down_sync(0xffffffffu, sm, off);
        sq += __shfl_down_sync(0xffffffffu, sq, off);
    }
    if (lane == 0) { wsum[tid >> 5] = sm; wsq[tid >> 5] = sq; }
    __syncthreads();
    if (tid == 0) {
        double ts = 0.0, tq = 0.0;
        #pragma unroll
        for (int w = 0; w < 8; w++) { ts += wsum[w]; tq += wsq[w]; }
        atomicAdd((unsigned long long*)&g_sumll[seg], (unsigned long long)__double2ll_rn(ts * SCST));
        atomicAdd((unsigned long long*)&g_sqll[seg],  (unsigned long long)__double2ll_rn(tq * SCST));
    }

    // peak count
    int loc = 0;
    for (int t = tid + 1; t < Ls - 1; t += TPB) {
        float v = wr[IDX(t)];
        if (v > wr[IDX(t-1)] && v > wr[IDX(t+1)]) loc++;
    }
    if (loc) atomicAdd(s_cnt, loc);
    __syncthreads();
    if (tid == 0) { *s_base = atomicAdd(&g_pcount[seg], *s_cnt); *s_cnt = 0; }
    __syncthreads();
    // ballot-aggregated peak write + pass-0 (12-bit) histogram
    unsigned* keys = g_pkeys + corrOff(sIdx) + (size_t)b * CH * Ls;
    unsigned* gh0 = g_h4k + (size_t)seg * 4096;
    int iters = Ls / TPB;
    for (int it = 0; it < iters; it++) {
        int t = it * TPB + tid + 1;
        bool pk = false; float v = 0.0f;
        if (t < Ls - 1) {
            v = wr[IDX(t)];
            pk = (v > wr[IDX(t-1)] && v > wr[IDX(t+1)]);
        }
        unsigned key = pk ? f2k(v * invN) : 0u;
        unsigned mask = __ballot_sync(0xffffffffu, pk);
        if (mask) {
            int leader = __ffs(mask) - 1;
            int wb = 0;
            if (lane == leader) wb = atomicAdd(s_cnt, __popc(mask));
            wb = __shfl_sync(0xffffffffu, wb, leader);
            if (pk) {
                int rank = __popc(mask & ((1u << lane) - 1u));
                keys[*s_base + wb + rank] = key;
            }
        }
        unsigned tag = pk ? (key >> 20) : 0xffffffffu;
        unsigned mm = __match_any_sync(0xffffffffu, tag);
        if (pk && lane == (__ffs(mm) - 1))
            atomicAdd(&gh0[key >> 20], (unsigned)__popc(mm));
    }
    __syncthreads();
}

// ---------------- fused corr: 1 fwd FFT + spectral pooling + 3 inverse FFTs per channel ----------------
__global__ void corr_fused_kernel() {
    extern __shared__ float smem[];
    __shared__ double wsum[8], wsq[8];
    __shared__ int s_cnt, s_base;
    int ch = blockIdx.x;
    int b  = ch >> 9;
    float* zr = smem;
    float* zi = smem + ZSTR;
    float* wr = smem + 2 * ZSTR;
    float* wi = smem + 3 * ZSTR;
    float2* tws = (float2*)(smem + 4 * ZSTR);   // 512 entries, 4 KB
    int tid = threadIdx.x;

    // cache 1024-pt twiddle table in smem (serves all sizes via index scaling)
    {
        float4 t = ((const float4*)g_twid)[tid];     // 256 threads x 2 float2
        ((float4*)tws)[tid] = t;
    }

    // coalesced load + bit-reversal scatter (logN=10)
    {
        float4 qa = ((const float4*)(g_qT + (size_t)ch * L_))[tid];
        float4 ka = ((const float4*)(g_kT + (size_t)ch * L_))[tid];
        int t0 = tid * 4;
        int r0 = IDX((int)(__brev((unsigned)(t0  )) >> 22));
        int r1 = IDX((int)(__brev((unsigned)(t0+1)) >> 22));
        int r2 = IDX((int)(__brev((unsigned)(t0+2)) >> 22));
        int r3 = IDX((int)(__brev((unsigned)(t0+3)) >> 22));
        zr[r0] = qa.x; zi[r0] = ka.x;
        zr[r1] = qa.y; zi[r1] = ka.y;
        zr[r2] = qa.z; zi[r2] = ka.z;
        zr[r3] = qa.w; zi[r3] = ka.w;
    }
    __syncthreads();

    fft_pairs(zr, zi, 1024, 10, tws, false, tid);   // Z natural order

    // ---- scale 0 ----
    split_mult(zr, zi, wr, wi, 1024, 22, tid);
    __syncthreads();
    fft_pairs(wr, wi, 1024, 10, tws, true, tid);
    epilogue(0, ch, b, b, 1024, wr, tid, wsum, wsq, &s_cnt, &s_base);

    // ---- scale 1 ----
    derive_half(zr, zi, 512, 0, tws, tid);
    __syncthreads();
    split_mult(zr, zi, wr, wi, 512, 23, tid);
    __syncthreads();
    fft_pairs(wr, wi, 512, 9, tws, true, tid);
    epilogue(1, ch, b, 16 + b, 512, wr, tid, wsum, wsq, &s_cnt, &s_base);

    // ---- scale 2 ----
    derive_half(zr, zi, 256, 1, tws, tid);
    __syncthreads();
    split_mult(zr, zi, wr, wi, 256, 24, tid);
    __syncthreads();
    fft_pairs(wr, wi, 256, 8, tws, true, tid);
    epilogue(2, ch, b, 32 + b, 256, wr, tid, wsum, wsq, &s_cnt, &s_base);
}

// ---------------- scan0: pk feature + MLP + scan pass-0 hist ----------------
__global__ void scan0_kernel(const float* __restrict__ w1, const float* __restrict__ b1,
                             const float* __restrict__ w2, const float* __restrict__ b2,
                             const float* __restrict__ w3, const float* __restrict__ b3) {
    __shared__ unsigned sscan[TPB];
    __shared__ int s_pkred[8];
    __shared__ int s_k;
    int seg = blockIdx.x;
    int sIdx = seg >> 4, b = seg & 15;
    int Ls = cLs[sIdx];
    int tid = threadIdx.x;
    int lane = tid & 31;
    unsigned* hist = g_h4k + (size_t)seg * 4096;

    const long long* cm = g_cmll + cCmSeg[sIdx] + b * Ls;
    int cnt = 0;
    for (int t = tid + 1; t < Ls - 1; t += TPB) {
        long long v = cm[t];
        if (v > cm[t - 1] && v > cm[t + 1]) cnt++;
    }
    #pragma unroll
    for (int off = 16; off > 0; off >>= 1) cnt += __shfl_down_sync(0xffffffffu, cnt, off);
    if (lane == 0) s_pkred[tid >> 5] = cnt;
    __syncthreads();
    if (tid == 0) {
        int pkc = 0;
        #pragma unroll
        for (int w = 0; w < 8; w++) pkc += s_pkred[w];
        const double invSC = 1.0 / SCST;
        float f2 = (float)pkc;
        long long tot = 0;
        for (int i = 0; i < B_; i++) tot += g_sqll[sIdx * 16 + i];
        float f0 = (float)((double)tot * invSC / ((double)B_ * (double)Ls));
        double n = (double)CH * (double)Ls;
        double s1 = (double)g_sumll[seg] * invSC;
        double s2 = (double)g_sqll[seg] * invSC;
        double mean = s1 / n;
        float f1 = (float)((s2 - mean * s1) / (n - 1.0));
        float h1[32];
        for (int j = 0; j < 32; j++) {
            float a = w1[j*3] * f0 + w1[j*3+1] * f1 + w1[j*3+2] * f2 + b1[j];
            h1[j] = a > 0.0f ? a : 0.0f;
        }
        float h2[16];
        for (int j = 0; j < 16; j++) {
            float a = b2[j];
            for (int i2 = 0; i2 < 32; i2++) a += w2[j*32+i2] * h1[i2];
            h2[j] = a > 0.0f ? a : 0.0f;
        }
        float a = b3[0];
        for (int i2 = 0; i2 < 16; i2++) a += w3[i2] * h2[i2];
        float ratio = 1.0f / (1.0f + expf(-a));
        int kv = (int)(ratio * (float)Ls);
        if (kv < 1) kv = 1;
        if (kv > Ls) kv = Ls;
        g_kvals[seg] = kv;
        s_k = kv;
    }
    __syncthreads();
    unsigned k = (unsigned)s_k;

    int cstart = tid * 16;
    unsigned myChunk = 0;
    uint4 hb[4];
    {
        const uint4* h4 = (const uint4*)(hist + cstart);
        #pragma unroll
        for (int j = 0; j < 4; j++) {
            hb[j] = h4[j];
            myChunk += hb[j].x + hb[j].y + hb[j].z + hb[j].w;
        }
    }
    sscan[tid] = myChunk;
    __syncthreads();
    for (int off = 1; off < TPB; off <<= 1) {
        unsigned v = (tid + off < TPB) ? sscan[tid + off] : 0u;
        __syncthreads();
        sscan[tid] += v;
        __syncthreads();
    }
    unsigned incl = sscan[tid];
    unsigned cumBefore = incl - myChunk;
    if (myChunk > 0 && cumBefore < k && incl >= k) {
        unsigned cum = cumBefore;
        unsigned bins[16] = {hb[0].x,hb[0].y,hb[0].z,hb[0].w, hb[1].x,hb[1].y,hb[1].z,hb[1].w,
                             hb[2].x,hb[2].y,hb[2].z,hb[2].w, hb[3].x,hb[3].y,hb[3].z,hb[3].w};
        for (int j = 15; j >= 0; --j) {
            unsigned h = bins[j];
            if (cum + h >= k) {
                g_prefix[seg] = (unsigned)(cstart + j) << 20;
                g_krem[seg] = (int)(k - cum);
                break;
            }
            cum += h;
        }
    }
    {
        uint4* h4 = (uint4*)(hist + cstart);
        #pragma unroll
        for (int j = 0; j < 4; j++) h4[j] = make_uint4(0u,0u,0u,0u);
    }
}

// ---------------- fused hist+scan for pass 1 (12 bits) and pass 2 (8 bits) ----------------
__global__ void histscan_kernel(int pass) {
    __shared__ unsigned hl[4096];
    __shared__ unsigned sscan[TPB];
    __shared__ int s_last, s_k;
    int seg = blockIdx.y;
    int sIdx = seg >> 4, b = seg & 15;
    int tid = threadIdx.x;
    int lane = tid & 31;
    unsigned* gh = g_h4k + (size_t)seg * 4096;
    unsigned* ctr = (pass == 1 ? g_done1 : g_done2) + seg;

    for (int i = tid; i < 4096; i += TPB) hl[i] = 0;
    __syncthreads();

    int cnt = g_pcount[seg];
    unsigned pref = g_prefix[seg];
    const unsigned* keys = g_pkeys + corrOff(sIdx) + (size_t)b * CH * cLs[sIdx];
    int stride = gridDim.x * TPB;
    int iters = (cnt + stride - 1) / stride;
    int i = blockIdx.x * TPB + tid;
    for (int it = 0; it < iters; it++, i += stride) {
        bool valid = (i < cnt);
        unsigned key = valid ? keys[i] : 0u;
        bool ok; unsigned bin;
        if (pass == 1) { ok = valid && ((key >> 20) == (pref >> 20)); bin = (key >> 8) & 0xfffu; }
        else           { ok = valid && ((key >> 8) == (pref >> 8));   bin = key & 0xffu; }
        unsigned tag = ok ? bin : 0xffffffffu;
        unsigned mm = __match_any_sync(0xffffffffu, tag);
        if (ok && lane == (__ffs(mm) - 1))
            atomicAdd(&hl[bin], (unsigned)__popc(mm));
    }
    __syncthreads();
    for (int j = tid; j < 4096; j += TPB)
        if (hl[j]) atomicAdd(&gh[j], hl[j]);
    __threadfence();
    if (tid == 0) {
        unsigned t = atomicAdd(ctr, 1u);
        s_last = (t == gridDim.x - 1) ? 1 : 0;
    }
    __syncthreads();
    if (!s_last) return;
    __threadfence();
    if (tid == 0) s_k = g_krem[seg];
    __syncthreads();
    unsigned k = (unsigned)s_k;

    int nb = (pass == 2) ? 256 : 4096;
    int bpt = nb / TPB;
    int cstart = tid * bpt;
    unsigned myChunk = 0;
    for (int j = 0; j < bpt; j++) myChunk += gh[cstart + j];
    sscan[tid] = myChunk;
    __syncthreads();
    for (int off = 1; off < TPB; off <<= 1) {
        unsigned v = (tid + off < TPB) ? sscan[tid + off] : 0u;
        __syncthreads();
        sscan[tid] += v;
        __syncthreads();
    }
    unsigned incl = sscan[tid];
    unsigned cumBefore = incl - myChunk;
    if (myChunk > 0 && cumBefore < k && incl >= k) {
        unsigned cum = cumBefore;
        for (int bin = cstart + bpt - 1; bin >= cstart; --bin) {
            unsigned h = gh[bin];
            if (cum + h >= k) {
                if (pass == 1) {
                    g_prefix[seg] = (pref & 0xfff00000u) | ((unsigned)bin << 8);
                    g_krem[seg] = (int)(k - cum);
                } else {
                    g_thresh[seg] = k2f((pref & 0xffffff00u) | (unsigned)bin);
                }
                break;
            }
            cum += h;
        }
    }
    __syncthreads();
    for (int j = tid; j < 4096; j += TPB) gh[j] = 0u;
    if (tid == 0) *ctr = 0u;
}

// ---------------- final: masked softmax * pooled v (pre-interp rows) ----------------
__global__ void final_all_kernel(const float* __restrict__ swarr) {
    extern __shared__ float smem[];
    __shared__ float red[TPB];
    int sIdx = blockIdx.x >> 13;
    int ch   = blockIdx.x & (NCH - 1);
    int b    = ch >> 9;
    int seg  = sIdx * 16 + b;
    int Ls = cLs[sIdx];
    int tid = threadIdx.x;
    float* sc = smem;
    float* so = smem + Ls;

    const float4* c4 = (const float4*)(g_corr + corrOff(sIdx) + (size_t)ch * Ls);
    int nv = Ls >> 2;
    if (tid < nv) ((float4*)sc)[tid] = c4[tid];
    __syncthreads();

    float thr = g_thresh[seg];
    bool useAll = (g_pcount[seg] <= g_kvals[seg]);

    float m = 0.0f;
    for (int t = tid; t < Ls; t += TPB) {
        float a = 0.0f;
        if (t > 0 && t < Ls - 1) {
            float v = sc[t];
            if (v > sc[t - 1] && v > sc[t + 1] && (useAll || v >= thr)) a = v;
        }
        so[t] = a;
        m = fmaxf(m, a);
    }
    red[tid] = m; __syncthreads();
    for (int o = TPB / 2; o > 0; o >>= 1) {
        if (tid < o) red[tid] = fmaxf(red[tid], red[tid + o]);
        __syncthreads();
    }
    m = red[0]; __syncthreads();

    float ds = 0.0f;
    for (int t = tid; t < Ls; t += TPB) {
        float e = __expf(so[t] - m);
        so[t] = e;
        ds += e;
    }
    red[tid] = ds; __syncthreads();
    for (int o = TPB / 2; o > 0; o >>= 1) {
        if (tid < o) red[tid] += red[tid + o];
        __syncthreads();
    }
    float inv = 1.0f / red[0];
    __syncthreads();

    float sw = swarr[sIdx];
    float c = sw * inv;
    {
        float4 vv = ((const float4*)(g_vT + (size_t)ch * L_))[tid];
        if (sIdx == 0) {
            int t0 = tid * 4;
            so[t0  ] = c * so[t0  ] * vv.x;
            so[t0+1] = c * so[t0+1] * vv.y;
            so[t0+2] = c * so[t0+2] * vv.z;
            so[t0+3] = c * so[t0+3] * vv.w;
        } else if (sIdx == 1) {
            int t0 = tid * 2;
            so[t0  ] = c * so[t0  ] * ((vv.x + vv.y) * 0.5f);
            so[t0+1] = c * so[t0+1] * ((vv.z + vv.w) * 0.5f);
        } else {
            so[tid] = c * so[tid] * ((vv.x + vv.y + vv.z + vv.w) * 0.25f);
        }
    }
    __syncthreads();

    float* outRow = g_wv + corrOff(sIdx) + (size_t)ch * Ls;
    if (tid < nv) ((float4*)outRow)[tid] = ((const float4*)so)[tid];
}

// ---------------- untranspose + on-the-fly interpolation + sum 3 scales ----------------
__global__ void untranspose_kernel(float* __restrict__ out) {
    __shared__ float tile[32][33];
    int b   = blockIdx.z;
    int ch0 = blockIdx.x * 32;
    int l0  = blockIdx.y * 32;
    int tx = threadIdx.x, ty = threadIdx.y;
    int l = l0 + tx;

    float s1 = 0.5f * (float)l - 0.25f;  if (s1 < 0.0f) s1 = 0.0f;
    int x10 = (int)s1; int x11 = x10 + 1; if (x11 > 511) x11 = 511;
    float lam1 = s1 - (float)x10;
    float s2 = 0.25f * (float)l - 0.375f; if (s2 < 0.0f) s2 = 0.0f;
    int x20 = (int)s2; int x21 = x20 + 1; if (x21 > 255) x21 = 255;
    float lam2 = s2 - (float)x20;

    const float* w1base = g_wv + (size_t)NCH * 1024;
    const float* w2base = g_wv + (size_t)NCH * 1536;

    for (int r = ty; r < 32; r += 8) {
        size_t ch = (size_t)b * CH + ch0 + r;
        const float* w0 = g_wv + ch * 1024;
        const float* w1 = w1base + ch * 512;
        const float* w2 = w2base + ch * 256;
        float v = w0[l]
                + w1[x10] * (1.0f - lam1) + w1[x11] * lam1
                + w2[x20] * (1.0f - lam2) + w2[x21] * lam2;
        tile[r][tx] = v;
    }
    __syncthreads();
    for (int r = ty; r < 32; r += 8)
        out[((size_t)b * L_ + (l0 + r)) * CH + ch0 + tx] = tile[tx][r];
}

// ---------------- launch ----------------
extern "C" void kernel_launch(void* const* d_in, const int* in_sizes, int n_in,
                              void* d_out, int out_size) {
    (void)in_sizes; (void)n_in; (void)out_size;
    const float* q  = (const float*)d_in[0];
    const float* kk = (const float*)d_in[1];
    const float* v  = (const float*)d_in[2];
    const float* sw = (const float*)d_in[3];
    const float* w1 = (const float*)d_in[4];
    const float* b1 = (const float*)d_in[5];
    const float* w2 = (const float*)d_in[6];
    const float* b2 = (const float*)d_in[7];
    const float* w3 = (const float*)d_in[8];
    const float* b3 = (const float*)d_in[9];
    float* out = (float*)d_out;

    init_kernel<<<64, TPB>>>();

    dim3 tgrid(CH / 32, L_ / 32, B_);
    dim3 tblk(32, 8);
    transpose3_kernel<<<tgrid, tblk>>>(q, kk, v);

    int fftSmem = 4 * ZSTR * sizeof(float) + 512 * sizeof(float2);   // 20992 B
    corr_fused_kernel<<<NCH, TPB, fftSmem>>>();

    scan0_kernel<<<NSEG, TPB>>>(w1, b1, w2, b2, w3, b3);
    dim3 hg(32, NSEG);
    histscan_kernel<<<hg, TPB>>>(1);
    histscan_kernel<<<hg, TPB>>>(2);

    final_all_kernel<<<3 * NCH, TPB, 2 * 1024 * sizeof(float)>>>(sw);

    untranspose_kernel<<<tgrid, tblk>>>(out);
}

// round 11
// speedup vs baseline: 1.2454x; 1.1910x over previous
#include <cuda_runtime.h>
#include <math.h>

#define B_ 16
#define L_ 1024
#define CH 512
#define NCH 8192        // B_*CH
#define TPB 256
#define NSEG 48         // 3 scales * 16 batches
#define TOTL 1792       // 1024+512+256

#define IDX(i) ((i) + ((i) >> 5))   // smem pad: conflict-free FFT strides
#define ZSTR 1056                    // buffer stride: IDX(1023)+2

// ---------------- static scratch ----------------
__device__ float     g_qT[(size_t)NCH*L_];
__device__ float     g_kT[(size_t)NCH*L_];
__device__ float     g_vT[(size_t)NCH*L_];
__device__ float     g_corr[(size_t)NCH*TOTL];
__device__ float     g_wv[(size_t)NCH*TOTL];      // weighted softmax*v rows (pre-interp)
__device__ unsigned  g_pkeys[(size_t)NCH*TOTL];
__device__ float2    g_twid[896];
__device__ float     g_cm[B_*TOTL];               // channel-sum rows (no atomics)
__device__ long long g_sumll[NSEG];
__device__ long long g_sqll[NSEG];
__device__ int       g_kvals[NSEG];
__device__ int       g_krem[NSEG];
__device__ unsigned  g_prefix[NSEG];
__device__ float     g_thresh[NSEG];
__device__ int       g_pcount[NSEG];
__device__ unsigned  g_h4k[(size_t)NSEG*4096];    // zero-init; self-cleaned every pass
__device__ unsigned  g_done0[NSEG];               // ticket counters; self-reset
__device__ unsigned  g_done1[NSEG];
__device__ unsigned  g_done2[NSEG];

__constant__ int    cLs[3]    = {1024, 512, 256};
__constant__ int    cCmSeg[3] = {0, 16384, 24576};

#define SCST 268435456.0      // 2^28 batch-stat fixed point (no int64 overflow)

__device__ __forceinline__ size_t corrOff(int s) {
    return s == 0 ? 0 : (s == 1 ? (size_t)NCH*1024 : (size_t)NCH*1536);
}
__device__ __forceinline__ unsigned f2k(float f) {
    unsigned u = __float_as_uint(f);
    return (u & 0x80000000u) ? ~u : (u | 0x80000000u);
}
__device__ __forceinline__ float k2f(unsigned k) {
    unsigned u = (k & 0x80000000u) ? (k & 0x7fffffffu) : ~k;
    return __uint_as_float(u);
}

// ---------------- init ----------------
__global__ void init_kernel() {
    int i = blockIdx.x * blockDim.x + threadIdx.x;
    int stride = gridDim.x * blockDim.x;
    if (i < NSEG) { g_sumll[i] = 0LL; g_sqll[i] = 0LL; g_pcount[i] = 0; }
    for (int j = i; j < 896; j += stride) {
        int N, jj;
        if (j < 512)      { N = 1024; jj = j; }
        else if (j < 768) { N = 512;  jj = j - 512; }
        else              { N = 256;  jj = j - 768; }
        double a = -6.283185307179586476925286766559 * (double)jj / (double)N;
        double sv, cv; sincos(a, &sv, &cv);
        g_twid[j] = make_float2((float)cv, (float)sv);
    }
}

// ---------------- transpose [B,L,CH] -> [B,CH,L] ----------------
__global__ void transpose3_kernel(const float* __restrict__ q,
                                  const float* __restrict__ k,
                                  const float* __restrict__ v) {
    __shared__ float tile[32][33];
    int b   = blockIdx.z;
    int ch0 = blockIdx.x * 32;
    int l0  = blockIdx.y * 32;
    const float* ins[3] = {q, k, v};
    float* outs[3] = {g_qT, g_kT, g_vT};
    int tx = threadIdx.x, ty = threadIdx.y;
    #pragma unroll
    for (int m = 0; m < 3; m++) {
        const float* in = ins[m];
        float* out = outs[m];
        for (int r = ty; r < 32; r += 8)
            tile[r][tx] = in[((size_t)b * L_ + (l0 + r)) * CH + ch0 + tx];
        __syncthreads();
        for (int r = ty; r < 32; r += 8)
            out[((size_t)b * CH + (ch0 + r)) * L_ + l0 + tx] = tile[tx][r];
        __syncthreads();
    }
}

// ---------------- radix-4 FFT on smem, twiddles from a shared 512-entry 1024-pt table ----------------
__device__ __forceinline__ void fft_pairs(float* sr, float* si, int N, int logN,
                                          const float2* tws, bool inv, int tid) {
    int st = 1;
    if (logN & 1) {
        for (int j = tid; j < (N >> 1); j += TPB) {
            int i0 = IDX(j << 1), i1 = IDX((j << 1) + 1);
            float ur = sr[i0], ui = si[i0], vr = sr[i1], vi = si[i1];
            sr[i0] = ur + vr; si[i0] = ui + vi;
            sr[i1] = ur - vr; si[i1] = ui - vi;
        }
        __syncthreads();
        st = 2;
    }
    int groups = N >> 2;
    for (; st < logN; st += 2) {
        int half = 1 << (st - 1);
        for (int g = tid; g < groups; g += TPB) {
            int pos = g & (half - 1);
            int blk = g >> (st - 1);
            int a0 = (blk << (st + 1)) + pos;
            int i0 = IDX(a0), i1 = IDX(a0 + half), i2 = IDX(a0 + 2*half), i3 = IDX(a0 + 3*half);
            float2 w  = tws[pos << (9 - st)];
            float2 w2 = tws[pos << (10 - st)];
            float wbr = w.x,  wbi = inv ? -w.y  : w.y;
            float war = w2.x, wai = inv ? -w2.y : w2.y;
            float a0r = sr[i0], a0i = si[i0], a1r = sr[i1], a1i = si[i1];
            float a2r = sr[i2], a2i = si[i2], a3r = sr[i3], a3i = si[i3];
            float t1r = war*a1r - wai*a1i, t1i = war*a1i + wai*a1r;
            float b0r = a0r + t1r, b0i = a0i + t1i;
            float b1r = a0r - t1r, b1i = a0i - t1i;
            float t3r = war*a3r - wai*a3i, t3i = war*a3i + wai*a3r;
            float b2r = a2r + t3r, b2i = a2i + t3i;
            float b3r = a2r - t3r, b3i = a2i - t3i;
            float u2r = wbr*b2r - wbi*b2i, u2i = wbr*b2i + wbi*b2r;
            float u3r = wbr*b3r - wbi*b3i, u3i = wbr*b3i + wbi*b3r;
            float vr3, vi3;
            if (!inv) { vr3 =  u3i; vi3 = -u3r; }
            else      { vr3 = -u3i; vi3 =  u3r; }
            sr[i0] = b0r + u2r; si[i0] = b0i + u2i;
            sr[i2] = b0r - u2r; si[i2] = b0i - u2i;
            sr[i1] = b1r + vr3; si[i1] = b1i + vi3;
            sr[i3] = b1r - vr3; si[i3] = b1i - vi3;
        }
        __syncthreads();
    }
}

__device__ __forceinline__ void split_mult(const float* zr, const float* zi,
                                           float* wr, float* wi, int Ls, int shv, int tid) {
    for (int f = tid; f <= Ls / 2; f += TPB) {
        int g = (Ls - f) & (Ls - 1);
        float a = zr[IDX(f)], bq = zi[IDX(f)];
        float c = zr[IDX(g)], d  = zi[IDX(g)];
        float qr = 0.5f * (a + c),  qi = 0.5f * (bq - d);
        float kr = 0.5f * (bq + d), ki = 0.5f * (a - c);
        float Sr = qr * kr - qi * ki;
        float Si = qr * ki + qi * kr;
        int pf = IDX((int)(__brev((unsigned)f) >> shv));
        int pg = IDX((int)(__brev((unsigned)g) >> shv));
        wr[pf] = Sr; wi[pf] = Si;
        wr[pg] = Sr; wi[pg] = -Si;
    }
}

__device__ __forceinline__ void derive_half(float* zr, float* zi, int Lout, int shiftTw,
                                            const float2* tws, int tid) {
    for (int f = tid; f < Lout; f += TPB) {
        float2 t = tws[f << shiftTw];
        float er = t.x, ei = -t.y;
        float ar = zr[IDX(f)],        ai = zi[IDX(f)];
        float br = zr[IDX(f + Lout)], bi = zi[IDX(f + Lout)];
        float p1r = ar * (1.0f + er) - ai * ei;
        float p1i = ai * (1.0f + er) + ar * ei;
        float p2r = br * (1.0f - er) + bi * ei;
        float p2i = bi * (1.0f - er) - br * ei;
        zr[IDX(f)] = 0.25f * (p1r + p2r);
        zi[IDX(f)] = 0.25f * (p1i + p2i);
    }
}

// Per-scale epilogue: corr write + stats + ballot-compacted peak keys. No contended atomics.
__device__ void epilogue(int sIdx, int ch, int b, int seg, int Ls, const float* wr,
                         int tid, double* wsum, double* wsq, int* s_cnt, int* s_base) {
    const float invN = 1.0f / (float)Ls;
    int lane = tid & 31;
    float* outRow = g_corr + corrOff(sIdx) + (size_t)ch * Ls;
    double sm = 0.0, sq = 0.0;
    int nv = Ls >> 2;
    if (tid == 0) *s_cnt = 0;
    if (tid < nv) {
        int t0 = tid * 4;
        int i0 = IDX(t0);
        float v0 = wr[i0] * invN, v1 = wr[i0+1] * invN, v2 = wr[i0+2] * invN, v3 = wr[i0+3] * invN;
        ((float4*)outRow)[tid] = make_float4(v0, v1, v2, v3);
        sm = (double)v0 + (double)v1 + (double)v2 + (double)v3;
        sq = (double)v0*v0 + (double)v1*v1 + (double)v2*v2 + (double)v3*v3;
    }
    #pragma unroll
    for (int off = 16; off > 0; off >>= 1) {
        sm += __shfl_down_sync(0xffffffffu, sm, off);
        sq += __shfl_down_sync(0xffffffffu, sq, off);
    }
    if (lane == 0) { wsum[tid >> 5] = sm; wsq[tid >> 5] = sq; }
    __syncthreads();
    if (tid == 0) {
        double ts = 0.0, tq = 0.0;
        #pragma unroll
        for (int w = 0; w < 8; w++) { ts += wsum[w]; tq += wsq[w]; }
        atomicAdd((unsigned long long*)&g_sumll[seg], (unsigned long long)__double2ll_rn(ts * SCST));
        atomicAdd((unsigned long long*)&g_sqll[seg],  (unsigned long long)__double2ll_rn(tq * SCST));
    }

    // peak count
    int loc = 0;
    for (int t = tid + 1; t < Ls - 1; t += TPB) {
        float v = wr[IDX(t)];
        if (v > wr[IDX(t-1)] && v > wr[IDX(t+1)]) loc++;
    }
    if (loc) atomicAdd(s_cnt, loc);
    __syncthreads();
    if (tid == 0) { *s_base = atomicAdd(&g_pcount[seg], *s_cnt); *s_cnt = 0; }
    __syncthreads();
    // ballot-aggregated peak key write
    unsigned* keys = g_pkeys + corrOff(sIdx) + (size_t)b * CH * Ls;
    int iters = Ls / TPB;
    for (int it = 0; it < iters; it++) {
        int t = it * TPB + tid + 1;
        bool pk = false; float v = 0.0f;
        if (t < Ls - 1) {
            v = wr[IDX(t)];
            pk = (v > wr[IDX(t-1)] && v > wr[IDX(t+1)]);
        }
        unsigned mask = __ballot_sync(0xffffffffu, pk);
        if (mask) {
            int leader = __ffs(mask) - 1;
            int wb = 0;
            if (lane == leader) wb = atomicAdd(s_cnt, __popc(mask));
            wb = __shfl_sync(0xffffffffu, wb, leader);
            if (pk) {
                int rank = __popc(mask & ((1u << lane) - 1u));
                keys[*s_base + wb + rank] = f2k(v * invN);
            }
        }
    }
    __syncthreads();
}

// ---------------- fused corr: 1 fwd FFT + spectral pooling + 3 inverse FFTs per channel ----------------
__global__ void corr_fused_kernel() {
    extern __shared__ float smem[];
    __shared__ double wsum[8], wsq[8];
    __shared__ int s_cnt, s_base;
    int ch = blockIdx.x;
    int b  = ch >> 9;
    float* zr = smem;
    float* zi = smem + ZSTR;
    float* wr = smem + 2 * ZSTR;
    float* wi = smem + 3 * ZSTR;
    float2* tws = (float2*)(smem + 4 * ZSTR);   // 512 entries, 4 KB
    int tid = threadIdx.x;

    {
        float4 t = ((const float4*)g_twid)[tid];
        ((float4*)tws)[tid] = t;
    }
    {
        float4 qa = ((const float4*)(g_qT + (size_t)ch * L_))[tid];
        float4 ka = ((const float4*)(g_kT + (size_t)ch * L_))[tid];
        int t0 = tid * 4;
        int r0 = IDX((int)(__brev((unsigned)(t0  )) >> 22));
        int r1 = IDX((int)(__brev((unsigned)(t0+1)) >> 22));
        int r2 = IDX((int)(__brev((unsigned)(t0+2)) >> 22));
        int r3 = IDX((int)(__brev((unsigned)(t0+3)) >> 22));
        zr[r0] = qa.x; zi[r0] = ka.x;
        zr[r1] = qa.y; zi[r1] = ka.y;
        zr[r2] = qa.z; zi[r2] = ka.z;
        zr[r3] = qa.w; zi[r3] = ka.w;
    }
    __syncthreads();

    fft_pairs(zr, zi, 1024, 10, tws, false, tid);

    split_mult(zr, zi, wr, wi, 1024, 22, tid);
    __syncthreads();
    fft_pairs(wr, wi, 1024, 10, tws, true, tid);
    epilogue(0, ch, b, b, 1024, wr, tid, wsum, wsq, &s_cnt, &s_base);

    derive_half(zr, zi, 512, 0, tws, tid);
    __syncthreads();
    split_mult(zr, zi, wr, wi, 512, 23, tid);
    __syncthreads();
    fft_pairs(wr, wi, 512, 9, tws, true, tid);
    epilogue(1, ch, b, 16 + b, 512, wr, tid, wsum, wsq, &s_cnt, &s_base);

    derive_half(zr, zi, 256, 1, tws, tid);
    __syncthreads();
    split_mult(zr, zi, wr, wi, 256, 24, tid);
    __syncthreads();
    fft_pairs(wr, wi, 256, 8, tws, true, tid);
    epilogue(2, ch, b, 32 + b, 256, wr, tid, wsum, wsq, &s_cnt, &s_base);
}

// ---------------- cm: per-(seg,t) channel sum over g_corr (deterministic, no atomics) ----------------
__global__ void cm_kernel() {
    int i = blockIdx.x * blockDim.x + threadIdx.x;
    if (i >= B_ * TOTL) return;
    int sIdx, b, t, Ls;
    if (i < 16384)      { sIdx = 0; Ls = 1024; int j = i;         b = j >> 10; t = j & 1023; }
    else if (i < 24576) { sIdx = 1; Ls = 512;  int j = i - 16384; b = j >> 9;  t = j & 511;  }
    else                { sIdx = 2; Ls = 256;  int j = i - 24576; b = j >> 8;  t = j & 255;  }
    const float* base = g_corr + corrOff(sIdx) + (size_t)b * CH * Ls + t;
    float a0 = 0.f, a1 = 0.f, a2 = 0.f, a3 = 0.f;
    #pragma unroll 4
    for (int ch = 0; ch < CH; ch += 4) {
        a0 += base[(size_t)ch * Ls];
        a1 += base[(size_t)(ch + 1) * Ls];
        a2 += base[(size_t)(ch + 2) * Ls];
        a3 += base[(size_t)(ch + 3) * Ls];
    }
    g_cm[i] = (a0 + a1) + (a2 + a3);   // scaling by 1/CH unnecessary for peak compare
}

// ---------------- fused hist+scan: pass 0 (12b, + MLP), pass 1 (12b), pass 2 (8b) ----------------
__global__ void histscan_kernel(int pass,
        const float* __restrict__ w1, const float* __restrict__ b1,
        const float* __restrict__ w2, const float* __restrict__ b2,
        const float* __restrict__ w3, const float* __restrict__ b3) {
    __shared__ unsigned hl[4096];
    __shared__ unsigned sscan[TPB];
    __shared__ int s_last, s_k;
    __shared__ int s_pkred[8];
    int seg = blockIdx.y;
    int sIdx = seg >> 4, b = seg & 15;
    int Ls = cLs[sIdx];
    int tid = threadIdx.x;
    int lane = tid & 31;
    unsigned* gh = g_h4k + (size_t)seg * 4096;
    unsigned* ctr = (pass == 0 ? g_done0 : (pass == 1 ? g_done1 : g_done2)) + seg;

    for (int i = tid; i < 4096; i += TPB) hl[i] = 0;
    __syncthreads();

    int cnt = g_pcount[seg];
    unsigned pref = (pass == 0) ? 0u : g_prefix[seg];
    const unsigned* keys = g_pkeys + corrOff(sIdx) + (size_t)b * CH * Ls;
    int stride = gridDim.x * TPB;
    int iters = (cnt + stride - 1) / stride;
    int i = blockIdx.x * TPB + tid;
    for (int it = 0; it < iters; it++, i += stride) {
        bool valid = (i < cnt);
        unsigned key = valid ? keys[i] : 0u;
        bool ok; unsigned bin;
        if (pass == 0)      { ok = valid;                                    bin = key >> 20; }
        else if (pass == 1) { ok = valid && ((key >> 20) == (pref >> 20));   bin = (key >> 8) & 0xfffu; }
        else                { ok = valid && ((key >> 8) == (pref >> 8));     bin = key & 0xffu; }
        unsigned tag = ok ? bin : 0xffffffffu;
        unsigned mm = __match_any_sync(0xffffffffu, tag);
        if (ok && lane == (__ffs(mm) - 1))
            atomicAdd(&hl[bin], (unsigned)__popc(mm));
    }
    __syncthreads();
    for (int j = tid; j < 4096; j += TPB)
        if (hl[j]) atomicAdd(&gh[j], hl[j]);
    __threadfence();
    if (tid == 0) {
        unsigned t = atomicAdd(ctr, 1u);
        s_last = (t == gridDim.x - 1) ? 1 : 0;
    }
    __syncthreads();
    if (!s_last) return;
    __threadfence();

    if (pass == 0) {
        // pk feature over cm + MLP -> k
        const float* cm = g_cm + cCmSeg[sIdx] + b * Ls;
        int pcnt = 0;
        for (int t = tid + 1; t < Ls - 1; t += TPB) {
            float v = cm[t];
            if (v > cm[t - 1] && v > cm[t + 1]) pcnt++;
        }
        #pragma unroll
        for (int off = 16; off > 0; off >>= 1) pcnt += __shfl_down_sync(0xffffffffu, pcnt, off);
        if (lane == 0) s_pkred[tid >> 5] = pcnt;
        __syncthreads();
        if (tid == 0) {
            int pkc = 0;
            #pragma unroll
            for (int w = 0; w < 8; w++) pkc += s_pkred[w];
            const double invSC = 1.0 / SCST;
            float f2 = (float)pkc;
            long long tot = 0;
            for (int ii = 0; ii < B_; ii++) tot += g_sqll[sIdx * 16 + ii];
            float f0 = (float)((double)tot * invSC / ((double)B_ * (double)Ls));
            double n = (double)CH * (double)Ls;
            double s1 = (double)g_sumll[seg] * invSC;
            double s2 = (double)g_sqll[seg] * invSC;
            double mean = s1 / n;
            float f1 = (float)((s2 - mean * s1) / (n - 1.0));
            float h1[32];
            for (int j = 0; j < 32; j++) {
                float a = w1[j*3] * f0 + w1[j*3+1] * f1 + w1[j*3+2] * f2 + b1[j];
                h1[j] = a > 0.0f ? a : 0.0f;
            }
            float h2[16];
            for (int j = 0; j < 16; j++) {
                float a = b2[j];
                for (int i2 = 0; i2 < 32; i2++) a += w2[j*32+i2] * h1[i2];
                h2[j] = a > 0.0f ? a : 0.0f;
            }
            float a = b3[0];
            for (int i2 = 0; i2 < 16; i2++) a += w3[i2] * h2[i2];
            float ratio = 1.0f / (1.0f + expf(-a));
            int kv = (int)(ratio * (float)Ls);
            if (kv < 1) kv = 1;
            if (kv > Ls) kv = Ls;
            g_kvals[seg] = kv;
            s_k = kv;
        }
    } else {
        if (tid == 0) s_k = g_krem[seg];
    }
    __syncthreads();
    unsigned k = (unsigned)s_k;

    int nb = (pass == 2) ? 256 : 4096;
    int bpt = nb / TPB;                 // 1 or 16
    int cstart = tid * bpt;
    unsigned myChunk = 0;
    for (int j = 0; j < bpt; j++) myChunk += gh[cstart + j];
    sscan[tid] = myChunk;
    __syncthreads();
    for (int off = 1; off < TPB; off <<= 1) {
        unsigned v = (tid + off < TPB) ? sscan[tid + off] : 0u;
        __syncthreads();
        sscan[tid] += v;
        __syncthreads();
    }
    unsigned incl = sscan[tid];
    unsigned cumBefore = incl - myChunk;
    if (myChunk > 0 && cumBefore < k && incl >= k) {
        unsigned cum = cumBefore;
        for (int bin = cstart + bpt - 1; bin >= cstart; --bin) {
            unsigned h = gh[bin];
            if (cum + h >= k) {
                if (pass == 0) {
                    g_prefix[seg] = (unsigned)bin << 20;
                    g_krem[seg] = (int)(k - cum);
                } else if (pass == 1) {
                    g_prefix[seg] = (pref & 0xfff00000u) | ((unsigned)bin << 8);
                    g_krem[seg] = (int)(k - cum);
                } else {
                    g_thresh[seg] = k2f((pref & 0xffffff00u) | (unsigned)bin);
                }
                break;
            }
            cum += h;
        }
    }
    __syncthreads();
    for (int j = tid; j < 4096; j += TPB) gh[j] = 0u;
    if (tid == 0) *ctr = 0u;
}

// ---------------- final: masked softmax * pooled v (pre-interp rows) ----------------
__global__ void final_all_kernel(const float* __restrict__ swarr) {
    extern __shared__ float smem[];
    __shared__ float red[TPB];
    int sIdx = blockIdx.x >> 13;
    int ch   = blockIdx.x & (NCH - 1);
    int b    = ch >> 9;
    int seg  = sIdx * 16 + b;
    int Ls = cLs[sIdx];
    int tid = threadIdx.x;
    float* sc = smem;
    float* so = smem + Ls;

    const float4* c4 = (const float4*)(g_corr + corrOff(sIdx) + (size_t)ch * Ls);
    int nv = Ls >> 2;
    if (tid < nv) ((float4*)sc)[tid] = c4[tid];
    __syncthreads();

    float thr = g_thresh[seg];
    bool useAll = (g_pcount[seg] <= g_kvals[seg]);

    float m = 0.0f;
    for (int t = tid; t < Ls; t += TPB) {
        float a = 0.0f;
        if (t > 0 && t < Ls - 1) {
            float v = sc[t];
            if (v > sc[t - 1] && v > sc[t + 1] && (useAll || v >= thr)) a = v;
        }
        so[t] = a;
        m = fmaxf(m, a);
    }
    red[tid] = m; __syncthreads();
    for (int o = TPB / 2; o > 0; o >>= 1) {
        if (tid < o) red[tid] = fmaxf(red[tid], red[tid + o]);
        __syncthreads();
    }
    m = red[0]; __syncthreads();

    float ds = 0.0f;
    for (int t = tid; t < Ls; t += TPB) {
        float e = __expf(so[t] - m);
        so[t] = e;
        ds += e;
    }
    red[tid] = ds; __syncthreads();
    for (int o = TPB / 2; o > 0; o >>= 1) {
        if (tid < o) red[tid] += red[tid + o];
        __syncthreads();
    }
    float inv = 1.0f / red[0];
    __syncthreads();

    float sw = swarr[sIdx];
    float c = sw * inv;
    {
        float4 vv = ((const float4*)(g_vT + (size_t)ch * L_))[tid];
        if (sIdx == 0) {
            int t0 = tid * 4;
            so[t0  ] = c * so[t0  ] * vv.x;
            so[t0+1] = c * so[t0+1] * vv.y;
            so[t0+2] = c * so[t0+2] * vv.z;
            so[t0+3] = c * so[t0+3] * vv.w;
        } else if (sIdx == 1) {
            int t0 = tid * 2;
            so[t0  ] = c * so[t0  ] * ((vv.x + vv.y) * 0.5f);
            so[t0+1] = c * so[t0+1] * ((vv.z + vv.w) * 0.5f);
        } else {
            so[tid] = c * so[tid] * ((vv.x + vv.y + vv.z + vv.w) * 0.25f);
        }
    }
    __syncthreads();

    float* outRow = g_wv + corrOff(sIdx) + (size_t)ch * Ls;
    if (tid < nv) ((float4*)outRow)[tid] = ((const float4*)so)[tid];
}

// ---------------- untranspose + on-the-fly interpolation + sum 3 scales ----------------
__global__ void untranspose_kernel(float* __restrict__ out) {
    __shared__ float tile[32][33];
    int b   = blockIdx.z;
    int ch0 = blockIdx.x * 32;
    int l0  = blockIdx.y * 32;
    int tx = threadIdx.x, ty = threadIdx.y;
    int l = l0 + tx;

    float s1 = 0.5f * (float)l - 0.25f;  if (s1 < 0.0f) s1 = 0.0f;
    int x10 = (int)s1; int x11 = x10 + 1; if (x11 > 511) x11 = 511;
    float lam1 = s1 - (float)x10;
    float s2 = 0.25f * (float)l - 0.375f; if (s2 < 0.0f) s2 = 0.0f;
    int x20 = (int)s2; int x21 = x20 + 1; if (x21 > 255) x21 = 255;
    float lam2 = s2 - (float)x20;

    const float* w1base = g_wv + (size_t)NCH * 1024;
    const float* w2base = g_wv + (size_t)NCH * 1536;

    for (int r = ty; r < 32; r += 8) {
        size_t ch = (size_t)b * CH + ch0 + r;
        const float* w0 = g_wv + ch * 1024;
        const float* w1 = w1base + ch * 512;
        const float* w2 = w2base + ch * 256;
        float v = w0[l]
                + w1[x10] * (1.0f - lam1) + w1[x11] * lam1
                + w2[x20] * (1.0f - lam2) + w2[x21] * lam2;
        tile[r][tx] = v;
    }
    __syncthreads();
    for (int r = ty; r < 32; r += 8)
        out[((size_t)b * L_ + (l0 + r)) * CH + ch0 + tx] = tile[tx][r];
}

// ---------------- launch ----------------
extern "C" void kernel_launch(void* const* d_in, const int* in_sizes, int n_in,
                              void* d_out, int out_size) {
    (void)in_sizes; (void)n_in; (void)out_size;
    const float* q  = (const float*)d_in[0];
    const float* kk = (const float*)d_in[1];
    const float* v  = (const float*)d_in[2];
    const float* sw = (const float*)d_in[3];
    const float* w1 = (const float*)d_in[4];
    const float* b1 = (const float*)d_in[5];
    const float* w2 = (const float*)d_in[6];
    const float* b2 = (const float*)d_in[7];
    const float* w3 = (const float*)d_in[8];
    const float* b3 = (const float*)d_in[9];
    float* out = (float*)d_out;

    init_kernel<<<64, TPB>>>();

    dim3 tgrid(CH / 32, L_ / 32, B_);
    dim3 tblk(32, 8);
    transpose3_kernel<<<tgrid, tblk>>>(q, kk, v);

    int fftSmem = 4 * ZSTR * sizeof(float) + 512 * sizeof(float2);   // 20992 B
    corr_fused_kernel<<<NCH, TPB, fftSmem>>>();

    cm_kernel<<<(B_ * TOTL + TPB - 1) / TPB, TPB>>>();

    dim3 hg(32, NSEG);
    histscan_kernel<<<hg, TPB>>>(0, w1, b1, w2, b2, w3, b3);
    histscan_kernel<<<hg, TPB>>>(1, w1, b1, w2, b2, w3, b3);
    histscan_kernel<<<hg, TPB>>>(2, w1, b1, w2, b2, w3, b3);

    final_all_kernel<<<3 * NCH, TPB, 2 * 1024 * sizeof(float)>>>(sw);

    untranspose_kernel<<<tgrid, tblk>>>(out);
}

// round 12
// speedup vs baseline: 1.3354x; 1.0722x over previous
#include <cuda_runtime.h>
#include <math.h>

#define B_ 16
#define L_ 1024
#define CH 512
#define NCH 8192        // B_*CH
#define TPB 256
#define NSEG 48         // 3 scales * 16 batches
#define TOTL 1792       // 1024+512+256

#define IDX(i) ((i) + ((i) >> 5))   // smem pad: conflict-free FFT strides
#define ZSTR 1056                    // buffer stride: IDX(1023)+2

// ---------------- static scratch ----------------
__device__ float     g_qT[(size_t)NCH*L_];
__device__ float     g_kT[(size_t)NCH*L_];
__device__ float     g_vT[(size_t)NCH*L_];
__device__ float     g_corr[(size_t)NCH*TOTL];
__device__ float     g_wv[(size_t)NCH*TOTL];      // weighted softmax*v rows (pre-interp)
__device__ unsigned  g_pkeys[(size_t)NCH*TOTL];
__device__ float2    g_twid[896];
__device__ float     g_cmp[(size_t)8*B_*TOTL];    // cm channel-partials
__device__ float     g_cm[B_*TOTL];               // channel-sum rows
__device__ long long g_sumll[NSEG];
__device__ long long g_sqll[NSEG];
__device__ int       g_kvals[NSEG];
__device__ int       g_krem[NSEG];
__device__ unsigned  g_prefix[NSEG];
__device__ float     g_thresh[NSEG];
__device__ int       g_pcount[NSEG];
__device__ unsigned  g_h4k[(size_t)NSEG*4096];    // zero-init; self-cleaned every pass
__device__ unsigned  g_done0[NSEG];               // ticket counters; self-reset
__device__ unsigned  g_done1[NSEG];
__device__ unsigned  g_done2[NSEG];

__constant__ int    cLs[3]    = {1024, 512, 256};
__constant__ int    cCmSeg[3] = {0, 16384, 24576};

#define SCST 268435456.0      // 2^28 batch-stat fixed point (no int64 overflow)

__device__ __forceinline__ size_t corrOff(int s) {
    return s == 0 ? 0 : (s == 1 ? (size_t)NCH*1024 : (size_t)NCH*1536);
}
__device__ __forceinline__ unsigned f2k(float f) {
    unsigned u = __float_as_uint(f);
    return (u & 0x80000000u) ? ~u : (u | 0x80000000u);
}
__device__ __forceinline__ float k2f(unsigned k) {
    unsigned u = (k & 0x80000000u) ? (k & 0x7fffffffu) : ~k;
    return __uint_as_float(u);
}

// ---------------- init ----------------
__global__ void init_kernel() {
    int i = blockIdx.x * blockDim.x + threadIdx.x;
    int stride = gridDim.x * blockDim.x;
    if (i < NSEG) { g_sumll[i] = 0LL; g_sqll[i] = 0LL; g_pcount[i] = 0; }
    for (int j = i; j < 896; j += stride) {
        int N, jj;
        if (j < 512)      { N = 1024; jj = j; }
        else if (j < 768) { N = 512;  jj = j - 512; }
        else              { N = 256;  jj = j - 768; }
        double a = -6.283185307179586476925286766559 * (double)jj / (double)N;
        double sv, cv; sincos(a, &sv, &cv);
        g_twid[j] = make_float2((float)cv, (float)sv);
    }
}

// ---------------- transpose [B,L,CH] -> [B,CH,L] ----------------
__global__ void transpose3_kernel(const float* __restrict__ q,
                                  const float* __restrict__ k,
                                  const float* __restrict__ v) {
    __shared__ float tile[32][33];
    int b   = blockIdx.z;
    int ch0 = blockIdx.x * 32;
    int l0  = blockIdx.y * 32;
    const float* ins[3] = {q, k, v};
    float* outs[3] = {g_qT, g_kT, g_vT};
    int tx = threadIdx.x, ty = threadIdx.y;
    #pragma unroll
    for (int m = 0; m < 3; m++) {
        const float* in = ins[m];
        float* out = outs[m];
        for (int r = ty; r < 32; r += 8)
            tile[r][tx] = in[((size_t)b * L_ + (l0 + r)) * CH + ch0 + tx];
        __syncthreads();
        for (int r = ty; r < 32; r += 8)
            out[((size_t)b * CH + (ch0 + r)) * L_ + l0 + tx] = tile[tx][r];
        __syncthreads();
    }
}

// ---------------- radix-4 FFT on smem, twiddles from shared 512-entry 1024-pt table ----------------
// tw_N[j] == tw1024[j * (1024/N)] => index formulas below are N-independent.
__device__ __forceinline__ void fft_pairs(float* sr, float* si, int N, int logN,
                                          const float2* tws, bool inv, int tid) {
    int st = 1;
    if (logN & 1) {
        for (int j = tid; j < (N >> 1); j += TPB) {
            int i0 = IDX(j << 1), i1 = IDX((j << 1) + 1);
            float ur = sr[i0], ui = si[i0], vr = sr[i1], vi = si[i1];
            sr[i0] = ur + vr; si[i0] = ui + vi;
            sr[i1] = ur - vr; si[i1] = ui - vi;
        }
        __syncthreads();
        st = 2;
    }
    int groups = N >> 2;
    for (; st < logN; st += 2) {
        int half = 1 << (st - 1);
        for (int g = tid; g < groups; g += TPB) {
            int pos = g & (half - 1);
            int blk = g >> (st - 1);
            int a0 = (blk << (st + 1)) + pos;
            int i0 = IDX(a0), i1 = IDX(a0 + half), i2 = IDX(a0 + 2*half), i3 = IDX(a0 + 3*half);
            float2 w  = tws[pos << (9 - st)];
            float2 w2 = tws[pos << (10 - st)];
            float wbr = w.x,  wbi = inv ? -w.y  : w.y;
            float war = w2.x, wai = inv ? -w2.y : w2.y;
            float a0r = sr[i0], a0i = si[i0], a1r = sr[i1], a1i = si[i1];
            float a2r = sr[i2], a2i = si[i2], a3r = sr[i3], a3i = si[i3];
            float t1r = war*a1r - wai*a1i, t1i = war*a1i + wai*a1r;
            float b0r = a0r + t1r, b0i = a0i + t1i;
            float b1r = a0r - t1r, b1i = a0i - t1i;
            float t3r = war*a3r - wai*a3i, t3i = war*a3i + wai*a3r;
            float b2r = a2r + t3r, b2i = a2i + t3i;
            float b3r = a2r - t3r, b3i = a2i - t3i;
            float u2r = wbr*b2r - wbi*b2i, u2i = wbr*b2i + wbi*b2r;
            float u3r = wbr*b3r - wbi*b3i, u3i = wbr*b3i + wbi*b3r;
            float vr3, vi3;
            if (!inv) { vr3 =  u3i; vi3 = -u3r; }
            else      { vr3 = -u3i; vi3 =  u3r; }
            sr[i0] = b0r + u2r; si[i0] = b0i + u2i;
            sr[i2] = b0r - u2r; si[i2] = b0i - u2i;
            sr[i1] = b1r + vr3; si[i1] = b1i + vi3;
            sr[i3] = b1r - vr3; si[i3] = b1i - vi3;
        }
        __syncthreads();
    }
}

// Fused Hermitian split + real-IFFT fold:
// From packed Z (natural order, length N) build Y[f] = E+iO (f in [0,M), M=N/2) where
//   S[f]=Q[f]conj(K[f]),  E=S[f]+S[f+M],  O=(S[f]-S[f+M])*conj(tw_N[f]),
// scattered bit-reversed (M-point) into w. After M-point inverse FFT:
//   corr[2m] = wr[m]/N, corr[2m+1] = wi[m]/N.
// Mirror identities used: S[M-f]=conj(S[f+M]), S[N-f]=conj(S[f]), conj(tw[M-f])=(-er,ei).
__device__ __forceinline__ void hermY(const float* zr, const float* zi,
                                      float* wr, float* wi, int N, int logM,
                                      int twShift, const float2* tws, int tid) {
    int M = N >> 1;
    int shvM = 32 - logM;
    for (int f = tid; f <= (M >> 1); f += TPB) {
        int g = (N - f) & (N - 1);
        float a = zr[IDX(f)], b = zi[IDX(f)];
        float c = zr[IDX(g)], d = zi[IDX(g)];
        float qr = 0.5f*(a + c), qi = 0.5f*(b - d);
        float kr = 0.5f*(b + d), ki = 0.5f*(a - c);
        float Sfr = qr*kr - qi*ki, Sfi = qr*ki + qi*kr;
        int f2 = f + M;
        int g2 = (N - f2) & (N - 1);
        float a2 = zr[IDX(f2)], b2 = zi[IDX(f2)];
        float c2 = zr[IDX(g2)], d2 = zi[IDX(g2)];
        float q2r = 0.5f*(a2 + c2), q2i = 0.5f*(b2 - d2);
        float k2r = 0.5f*(b2 + d2), k2i = 0.5f*(a2 - c2);
        float S2r = q2r*k2r - q2i*k2i, S2i = q2r*k2i + q2i*k2r;

        float2 t = tws[f << twShift];
        float er = t.x, ei = -t.y;          // conj(tw_N[f])
        float Er = Sfr + S2r, Ei = Sfi + S2i;
        float Dr = Sfr - S2r, Di = Sfi - S2i;
        float Or = Dr*er - Di*ei, Oi = Dr*ei + Di*er;

        int pf = IDX((int)(__brev((unsigned)f) >> shvM));
        wr[pf] = Er - Oi; wi[pf] = Ei + Or;
        if (f != 0 && f != (M >> 1)) {
            int m2 = M - f;
            int pm = IDX((int)(__brev((unsigned)m2) >> shvM));
            wr[pm] = Er + Oi; wi[pm] = Or - Ei;
        }
    }
}

// derive pooled packed spectrum (unchanged)
__device__ __forceinline__ void derive_half(float* zr, float* zi, int Lout, int shiftTw,
                                            const float2* tws, int tid) {
    for (int f = tid; f < Lout; f += TPB) {
        float2 t = tws[f << shiftTw];
        float er = t.x, ei = -t.y;
        float ar = zr[IDX(f)],        ai = zi[IDX(f)];
        float br = zr[IDX(f + Lout)], bi = zi[IDX(f + Lout)];
        float p1r = ar * (1.0f + er) - ai * ei;
        float p1i = ai * (1.0f + er) + ar * ei;
        float p2r = br * (1.0f - er) + bi * ei;
        float p2i = bi * (1.0f - er) - br * ei;
        zr[IDX(f)] = 0.25f * (p1r + p2r);
        zi[IDX(f)] = 0.25f * (p1i + p2i);
    }
}

// interleaved corr value: corr[t] (unnormalized) lives in wr/wi half-size buffers
__device__ __forceinline__ float cval(const float* wr, const float* wi, int t) {
    int m = t >> 1;
    return (t & 1) ? wi[IDX(m)] : wr[IDX(m)];
}

// Per-scale epilogue: corr write + stats + ballot-compacted peak keys.
__device__ void epilogue(int sIdx, int ch, int b, int seg, int Ls,
                         const float* wr, const float* wi,
                         int tid, double* wsum, double* wsq, int* s_cnt, int* s_base) {
    const float invN = 1.0f / (float)Ls;
    int lane = tid & 31;
    float* outRow = g_corr + corrOff(sIdx) + (size_t)ch * Ls;
    double sm = 0.0, sq = 0.0;
    int nv = Ls >> 2;
    if (tid == 0) *s_cnt = 0;
    if (tid < nv) {
        int m0 = 2 * tid;
        float v0 = wr[IDX(m0)]   * invN, v1 = wi[IDX(m0)]   * invN;
        float v2 = wr[IDX(m0+1)] * invN, v3 = wi[IDX(m0+1)] * invN;
        ((float4*)outRow)[tid] = make_float4(v0, v1, v2, v3);
        sm = (double)v0 + (double)v1 + (double)v2 + (double)v3;
        sq = (double)v0*v0 + (double)v1*v1 + (double)v2*v2 + (double)v3*v3;
    }
    #pragma unroll
    for (int off = 16; off > 0; off >>= 1) {
        sm += __shfl_down_sync(0xffffffffu, sm, off);
        sq += __shfl_down_sync(0xffffffffu, sq, off);
    }
    if (lane == 0) { wsum[tid >> 5] = sm; wsq[tid >> 5] = sq; }
    __syncthreads();
    if (tid == 0) {
        double ts = 0.0, tq = 0.0;
        #pragma unroll
        for (int w = 0; w < 8; w++) { ts += wsum[w]; tq += wsq[w]; }
        atomicAdd((unsigned long long*)&g_sumll[seg], (unsigned long long)__double2ll_rn(ts * SCST));
        atomicAdd((unsigned long long*)&g_sqll[seg],  (unsigned long long)__double2ll_rn(tq * SCST));
    }

    // peak count
    int loc = 0;
    for (int t = tid + 1; t < Ls - 1; t += TPB) {
        float v = cval(wr, wi, t);
        if (v > cval(wr, wi, t-1) && v > cval(wr, wi, t+1)) loc++;
    }
    if (loc) atomicAdd(s_cnt, loc);
    __syncthreads();
    if (tid == 0) { *s_base = atomicAdd(&g_pcount[seg], *s_cnt); *s_cnt = 0; }
    __syncthreads();
    // ballot-aggregated peak key write
    unsigned* keys = g_pkeys + corrOff(sIdx) + (size_t)b * CH * Ls;
    int iters = Ls / TPB;
    for (int it = 0; it < iters; it++) {
        int t = it * TPB + tid + 1;
        bool pk = false; float v = 0.0f;
        if (t < Ls - 1) {
            v = cval(wr, wi, t);
            pk = (v > cval(wr, wi, t-1) && v > cval(wr, wi, t+1));
        }
        unsigned mask = __ballot_sync(0xffffffffu, pk);
        if (mask) {
            int leader = __ffs(mask) - 1;
            int wb = 0;
            if (lane == leader) wb = atomicAdd(s_cnt, __popc(mask));
            wb = __shfl_sync(0xffffffffu, wb, leader);
            if (pk) {
                int rank = __popc(mask & ((1u << lane) - 1u));
                keys[*s_base + wb + rank] = f2k(v * invN);
            }
        }
    }
    __syncthreads();
}

// ---------------- fused corr: 1 fwd 1024 FFT + spectral pooling + 3 half-size inverse FFTs ----------------
__global__ void corr_fused_kernel() {
    extern __shared__ float smem[];
    __shared__ double wsum[8], wsq[8];
    __shared__ int s_cnt, s_base;
    int ch = blockIdx.x;
    int b  = ch >> 9;
    float* zr = smem;
    float* zi = smem + ZSTR;
    float* wr = smem + 2 * ZSTR;
    float* wi = smem + 3 * ZSTR;
    float2* tws = (float2*)(smem + 4 * ZSTR);   // 512 entries, 4 KB
    int tid = threadIdx.x;

    {
        float4 t = ((const float4*)g_twid)[tid];
        ((float4*)tws)[tid] = t;
    }
    {
        float4 qa = ((const float4*)(g_qT + (size_t)ch * L_))[tid];
        float4 ka = ((const float4*)(g_kT + (size_t)ch * L_))[tid];
        int t0 = tid * 4;
        int r0 = IDX((int)(__brev((unsigned)(t0  )) >> 22));
        int r1 = IDX((int)(__brev((unsigned)(t0+1)) >> 22));
        int r2 = IDX((int)(__brev((unsigned)(t0+2)) >> 22));
        int r3 = IDX((int)(__brev((unsigned)(t0+3)) >> 22));
        zr[r0] = qa.x; zi[r0] = ka.x;
        zr[r1] = qa.y; zi[r1] = ka.y;
        zr[r2] = qa.z; zi[r2] = ka.z;
        zr[r3] = qa.w; zi[r3] = ka.w;
    }
    __syncthreads();

    fft_pairs(zr, zi, 1024, 10, tws, false, tid);   // packed forward FFT, natural order

    // scale 0: N=1024 -> 512-pt IFFT
    hermY(zr, zi, wr, wi, 1024, 9, 0, tws, tid);
    __syncthreads();
    fft_pairs(wr, wi, 512, 9, tws, true, tid);
    epilogue(0, ch, b, b, 1024, wr, wi, tid, wsum, wsq, &s_cnt, &s_base);

    // scale 1: derive pooled spectrum (N=512) -> 256-pt IFFT
    derive_half(zr, zi, 512, 0, tws, tid);
    __syncthreads();
    hermY(zr, zi, wr, wi, 512, 8, 1, tws, tid);
    __syncthreads();
    fft_pairs(wr, wi, 256, 8, tws, true, tid);
    epilogue(1, ch, b, 16 + b, 512, wr, wi, tid, wsum, wsq, &s_cnt, &s_base);

    // scale 2: derive pooled spectrum (N=256) -> 128-pt IFFT
    derive_half(zr, zi, 256, 1, tws, tid);
    __syncthreads();
    hermY(zr, zi, wr, wi, 256, 7, 2, tws, tid);
    __syncthreads();
    fft_pairs(wr, wi, 128, 7, tws, true, tid);
    epilogue(2, ch, b, 32 + b, 256, wr, wi, tid, wsum, wsq, &s_cnt, &s_base);
}

// ---------------- cm: 8-way channel-partial sums + combine (deterministic, no atomics) ----------------
__global__ void cm_part_kernel() {
    int idx = blockIdx.x * blockDim.x + threadIdx.x;
    if (idx >= 8 * B_ * TOTL) return;
    int i    = idx % (B_ * TOTL);
    int part = idx / (B_ * TOTL);
    int sIdx, b, t, Ls;
    if (i < 16384)      { sIdx = 0; Ls = 1024; int j = i;         b = j >> 10; t = j & 1023; }
    else if (i < 24576) { sIdx = 1; Ls = 512;  int j = i - 16384; b = j >> 9;  t = j & 511;  }
    else                { sIdx = 2; Ls = 256;  int j = i - 24576; b = j >> 8;  t = j & 255;  }
    const float* base = g_corr + corrOff(sIdx) + (size_t)(b * CH + part * 64) * Ls + t;
    float a0 = 0.f, a1 = 0.f, a2 = 0.f, a3 = 0.f;
    #pragma unroll 4
    for (int ch = 0; ch < 64; ch += 4) {
        a0 += base[(size_t)ch * Ls];
        a1 += base[(size_t)(ch + 1) * Ls];
        a2 += base[(size_t)(ch + 2) * Ls];
        a3 += base[(size_t)(ch + 3) * Ls];
    }
    g_cmp[idx] = (a0 + a1) + (a2 + a3);
}

__global__ void cm_combine_kernel() {
    int i = blockIdx.x * blockDim.x + threadIdx.x;
    if (i >= B_ * TOTL) return;
    float s = 0.0f;
    #pragma unroll
    for (int p = 0; p < 8; p++) s += g_cmp[(size_t)p * (B_ * TOTL) + i];
    g_cm[i] = s;   // 1/CH scaling unnecessary for peak compare
}

// ---------------- fused hist+scan: pass 0 (12b, + MLP), pass 1 (12b), pass 2 (8b) ----------------
__global__ void histscan_kernel(int pass,
        const float* __restrict__ w1, const float* __restrict__ b1,
        const float* __restrict__ w2, const float* __restrict__ b2,
        const float* __restrict__ w3, const float* __restrict__ b3) {
    __shared__ unsigned hl[4096];
    __shared__ unsigned sscan[TPB];
    __shared__ int s_last, s_k;
    __shared__ int s_pkred[8];
    int seg = blockIdx.y;
    int sIdx = seg >> 4, b = seg & 15;
    int Ls = cLs[sIdx];
    int tid = threadIdx.x;
    int lane = tid & 31;
    unsigned* gh = g_h4k + (size_t)seg * 4096;
    unsigned* ctr = (pass == 0 ? g_done0 : (pass == 1 ? g_done1 : g_done2)) + seg;

    for (int i = tid; i < 4096; i += TPB) hl[i] = 0;
    __syncthreads();

    int cnt = g_pcount[seg];
    unsigned pref = (pass == 0) ? 0u : g_prefix[seg];
    const unsigned* keys = g_pkeys + corrOff(sIdx) + (size_t)b * CH * Ls;
    int stride = gridDim.x * TPB;
    int iters = (cnt + stride - 1) / stride;
    int i = blockIdx.x * TPB + tid;
    for (int it = 0; it < iters; it++, i += stride) {
        bool valid = (i < cnt);
        unsigned key = valid ? keys[i] : 0u;
        bool ok; unsigned bin;
        if (pass == 0)      { ok = valid;                                    bin = key >> 20; }
        else if (pass == 1) { ok = valid && ((key >> 20) == (pref >> 20));   bin = (key >> 8) & 0xfffu; }
        else                { ok = valid && ((key >> 8) == (pref >> 8));     bin = key & 0xffu; }
        unsigned tag = ok ? bin : 0xffffffffu;
        unsigned mm = __match_any_sync(0xffffffffu, tag);
        if (ok && lane == (__ffs(mm) - 1))
            atomicAdd(&hl[bin], (unsigned)__popc(mm));
    }
    __syncthreads();
    for (int j = tid; j < 4096; j += TPB)
        if (hl[j]) atomicAdd(&gh[j], hl[j]);
    __threadfence();
    if (tid == 0) {
        unsigned t = atomicAdd(ctr, 1u);
        s_last = (t == gridDim.x - 1) ? 1 : 0;
    }
    __syncthreads();
    if (!s_last) return;
    __threadfence();

    if (pass == 0) {
        const float* cm = g_cm + cCmSeg[sIdx] + b * Ls;
        int pcnt = 0;
        for (int t = tid + 1; t < Ls - 1; t += TPB) {
            float v = cm[t];
            if (v > cm[t - 1] && v > cm[t + 1]) pcnt++;
        }
        #pragma unroll
        for (int off = 16; off > 0; off >>= 1) pcnt += __shfl_down_sync(0xffffffffu, pcnt, off);
        if (lane == 0) s_pkred[tid >> 5] = pcnt;
        __syncthreads();
        if (tid == 0) {
            int pkc = 0;
            #pragma unroll
            for (int w = 0; w < 8; w++) pkc += s_pkred[w];
            const double invSC = 1.0 / SCST;
            float f2 = (float)pkc;
            long long tot = 0;
            for (int ii = 0; ii < B_; ii++) tot += g_sqll[sIdx * 16 + ii];
            float f0 = (float)((double)tot * invSC / ((double)B_ * (double)Ls));
            double n = (double)CH * (double)Ls;
            double s1 = (double)g_sumll[seg] * invSC;
            double s2 = (double)g_sqll[seg] * invSC;
            double mean = s1 / n;
            float f1 = (float)((s2 - mean * s1) / (n - 1.0));
            float h1[32];
            for (int j = 0; j < 32; j++) {
                float a = w1[j*3] * f0 + w1[j*3+1] * f1 + w1[j*3+2] * f2 + b1[j];
                h1[j] = a > 0.0f ? a : 0.0f;
            }
            float h2[16];
            for (int j = 0; j < 16; j++) {
                float a = b2[j];
                for (int i2 = 0; i2 < 32; i2++) a += w2[j*32+i2] * h1[i2];
                h2[j] = a > 0.0f ? a : 0.0f;
            }
            float a = b3[0];
            for (int i2 = 0; i2 < 16; i2++) a += w3[i2] * h2[i2];
            float ratio = 1.0f / (1.0f + expf(-a));
            int kv = (int)(ratio * (float)Ls);
            if (kv < 1) kv = 1;
            if (kv > Ls) kv = Ls;
            g_kvals[seg] = kv;
            s_k = kv;
        }
    } else {
        if (tid == 0) s_k = g_krem[seg];
    }
    __syncthreads();
    unsigned k = (unsigned)s_k;

    int nb = (pass == 2) ? 256 : 4096;
    int bpt = nb / TPB;                 // 1 or 16
    int cstart = tid * bpt;
    unsigned myChunk = 0;
    for (int j = 0; j < bpt; j++) myChunk += gh[cstart + j];
    sscan[tid] = myChunk;
    __syncthreads();
    for (int off = 1; off < TPB; off <<= 1) {
        unsigned v = (tid + off < TPB) ? sscan[tid + off] : 0u;
        __syncthreads();
        sscan[tid] += v;
        __syncthreads();
    }
    unsigned incl = sscan[tid];
    unsigned cumBefore = incl - myChunk;
    if (myChunk > 0 && cumBefore < k && incl >= k) {
        unsigned cum = cumBefore;
        for (int bin = cstart + bpt - 1; bin >= cstart; --bin) {
            unsigned h = gh[bin];
            if (cum + h >= k) {
                if (pass == 0) {
                    g_prefix[seg] = (unsigned)bin << 20;
                    g_krem[seg] = (int)(k - cum);
                } else if (pass == 1) {
                    g_prefix[seg] = (pref & 0xfff00000u) | ((unsigned)bin << 8);
                    g_krem[seg] = (int)(k - cum);
                } else {
                    g_thresh[seg] = k2f((pref & 0xffffff00u) | (unsigned)bin);
                }
                break;
            }
            cum += h;
        }
    }
    __syncthreads();
    for (int j = tid; j < 4096; j += TPB) gh[j] = 0u;
    if (tid == 0) *ctr = 0u;
}

// ---------------- final: masked softmax * pooled v (pre-interp rows) ----------------
__global__ void final_all_kernel(const float* __restrict__ swarr) {
    extern __shared__ float smem[];
    __shared__ float red[TPB];
    int sIdx = blockIdx.x >> 13;
    int ch   = blockIdx.x & (NCH - 1);
    int b    = ch >> 9;
    int seg  = sIdx * 16 + b;
    int Ls = cLs[sIdx];
    int tid = threadIdx.x;
    float* sc = smem;
    float* so = smem + Ls;

    const float4* c4 = (const float4*)(g_corr + corrOff(sIdx) + (size_t)ch * Ls);
    int nv = Ls >> 2;
    if (tid < nv) ((float4*)sc)[tid] = c4[tid];
    __syncthreads();

    float thr = g_thresh[seg];
    bool useAll = (g_pcount[seg] <= g_kvals[seg]);

    float m = 0.0f;
    for (int t = tid; t < Ls; t += TPB) {
        float a = 0.0f;
        if (t > 0 && t < Ls - 1) {
            float v = sc[t];
            if (v > sc[t - 1] && v > sc[t + 1] && (useAll || v >= thr)) a = v;
        }
        so[t] = a;
        m = fmaxf(m, a);
    }
    red[tid] = m; __syncthreads();
    for (int o = TPB / 2; o > 0; o >>= 1) {
        if (tid < o) red[tid] = fmaxf(red[tid], red[tid + o]);
        __syncthreads();
    }
    m = red[0]; __syncthreads();

    float ds = 0.0f;
    for (int t = tid; t < Ls; t += TPB) {
        float e = __expf(so[t] - m);
        so[t] = e;
        ds += e;
    }
    red[tid] = ds; __syncthreads();
    for (int o = TPB / 2; o > 0; o >>= 1) {
        if (tid < o) red[tid] += red[tid + o];
        __syncthreads();
    }
    float inv = 1.0f / red[0];
    __syncthreads();

    float sw = swarr[sIdx];
    float c = sw * inv;
    {
        float4 vv = ((const float4*)(g_vT + (size_t)ch * L_))[tid];
        if (sIdx == 0) {
            int t0 = tid * 4;
            so[t0  ] = c * so[t0  ] * vv.x;
            so[t0+1] = c * so[t0+1] * vv.y;
            so[t0+2] = c * so[t0+2] * vv.z;
            so[t0+3] = c * so[t0+3] * vv.w;
        } else if (sIdx == 1) {
            int t0 = tid * 2;
            so[t0  ] = c * so[t0  ] * ((vv.x + vv.y) * 0.5f);
            so[t0+1] = c * so[t0+1] * ((vv.z + vv.w) * 0.5f);
        } else {
            so[tid] = c * so[tid] * ((vv.x + vv.y + vv.z + vv.w) * 0.25f);
        }
    }
    __syncthreads();

    float* outRow = g_wv + corrOff(sIdx) + (size_t)ch * Ls;
    if (tid < nv) ((float4*)outRow)[tid] = ((const float4*)so)[tid];
}

// ---------------- untranspose + on-the-fly interpolation + sum 3 scales ----------------
__global__ void untranspose_kernel(float* __restrict__ out) {
    __shared__ float tile[32][33];
    int b   = blockIdx.z;
    int ch0 = blockIdx.x * 32;
    int l0  = blockIdx.y * 32;
    int tx = threadIdx.x, ty = threadIdx.y;
    int l = l0 + tx;

    float s1 = 0.5f * (float)l - 0.25f;  if (s1 < 0.0f) s1 = 0.0f;
    int x10 = (int)s1; int x11 = x10 + 1; if (x11 > 511) x11 = 511;
    float lam1 = s1 - (float)x10;
    float s2 = 0.25f * (float)l - 0.375f; if (s2 < 0.0f) s2 = 0.0f;
    int x20 = (int)s2; int x21 = x20 + 1; if (x21 > 255) x21 = 255;
    float lam2 = s2 - (float)x20;

    const float* w1base = g_wv + (size_t)NCH * 1024;
    const float* w2base = g_wv + (size_t)NCH * 1536;

    for (int r = ty; r < 32; r += 8) {
        size_t ch = (size_t)b * CH + ch0 + r;
        const float* w0 = g_wv + ch * 1024;
        const float* w1 = w1base + ch * 512;
        const float* w2 = w2base + ch * 256;
        float v = w0[l]
                + w1[x10] * (1.0f - lam1) + w1[x11] * lam1
                + w2[x20] * (1.0f - lam2) + w2[x21] * lam2;
        tile[r][tx] = v;
    }
    __syncthreads();
    for (int r = ty; r < 32; r += 8)
        out[((size_t)b * L_ + (l0 + r)) * CH + ch0 + tx] = tile[tx][r];
}

// ---------------- launch ----------------
extern "C" void kernel_launch(void* const* d_in, const int* in_sizes, int n_in,
                              void* d_out, int out_size) {
    (void)in_sizes; (void)n_in; (void)out_size;
    const float* q  = (const float*)d_in[0];
    const float* kk = (const float*)d_in[1];
    const float* v  = (const float*)d_in[2];
    const float* sw = (const float*)d_in[3];
    const float* w1 = (const float*)d_in[4];
    const float* b1 = (const float*)d_in[5];
    const float* w2 = (const float*)d_in[6];
    const float* b2 = (const float*)d_in[7];
    const float* w3 = (const float*)d_in[8];
    const float* b3 = (const float*)d_in[9];
    float* out = (float*)d_out;

    init_kernel<<<64, TPB>>>();

    dim3 tgrid(CH / 32, L_ / 32, B_);
    dim3 tblk(32, 8);
    transpose3_kernel<<<tgrid, tblk>>>(q, kk, v);

    int fftSmem = 4 * ZSTR * sizeof(float) + 512 * sizeof(float2);   // 20992 B
    corr_fused_kernel<<<NCH, TPB, fftSmem>>>();

    cm_part_kernel<<<(8 * B_ * TOTL + TPB - 1) / TPB, TPB>>>();
    cm_combine_kernel<<<(B_ * TOTL + TPB - 1) / TPB, TPB>>>();

    dim3 hg(32, NSEG);
    histscan_kernel<<<hg, TPB>>>(0, w1, b1, w2, b2, w3, b3);
    histscan_kernel<<<hg, TPB>>>(1, w1, b1, w2, b2, w3, b3);
    histscan_kernel<<<hg, TPB>>>(2, w1, b1, w2, b2, w3, b3);

    final_all_kernel<<<3 * NCH, TPB, 2 * 1024 * sizeof(float)>>>(sw);

    untranspose_kernel<<<tgrid, tblk>>>(out);
}